// round 7
// baseline (speedup 1.0000x reference)
#include <cuda_runtime.h>
#include <cuda_fp16.h>
#include <cstdint>
#include <cstddef>

// ---------------- problem constants ----------------
#define BATCH   256
#define NTOK    50
#define NP      7
#define HID     256
#define HEADS   8
#define DH      32
#define MLPD    1024
#define OUTD    1000
#define PS      32
#define IMG     224
#define INPUTD  3072
#define ROWS    (BATCH*NTOK)      // 12800
#define PROWS   (BATCH*NP*NP)     // 12544
#define EMAX    512
#define IMGELEM (BATCH*3*IMG*IMG) // 38535168

// ---------------- device scratch ----------------
__device__ float    g_x[ROWS*HID];
__device__ float    g_h[ROWS*HID];
__device__ float    g_als[ROWS*HEADS];
__device__ float    g_ald[ROWS*HEADS];
__device__ float    g_alpha[(size_t)BATCH*EMAX*HEADS];
__device__ float    g_logits[BATCH*OUTD];
__device__ int      g_csr_ptr[NTOK+1];
__device__ int      g_csr_src[1024];
// fp16 hi/lo operand buffers (u32 = packed half2)
__device__ unsigned g_imgH[IMGELEM/2], g_imgL[IMGELEM/2];
__device__ unsigned g_yH[ROWS*HID/2],  g_yL[ROWS*HID/2];
__device__ unsigned g_mlpH[ROWS*MLPD/2], g_mlpL[ROWS*MLPD/2];
__device__ unsigned g_WmapH[(INPUTD/2)*HID],  g_WmapL[(INPUTD/2)*HID];
__device__ unsigned g_WgatH[4*(HID/2)*HID],   g_WgatL[4*(HID/2)*HID];
__device__ unsigned g_W1H[4*(HID/2)*MLPD],    g_W1L[4*(HID/2)*MLPD];
__device__ unsigned g_W2H[4*(MLPD/2)*HID],    g_W2L[4*(MLPD/2)*HID];

// ---------------- helpers ----------------
__device__ __forceinline__ float warpSum(float v){
    #pragma unroll
    for (int o=16;o;o>>=1) v += __shfl_xor_sync(0xffffffffu, v, o);
    return v;
}
__device__ __forceinline__ float warpMax(float v){
    #pragma unroll
    for (int o=16;o;o>>=1) v = fmaxf(v, __shfl_xor_sync(0xffffffffu, v, o));
    return v;
}
__device__ __forceinline__ float blockSum(float v, float* sm){
    int lane = threadIdx.x & 31, w = threadIdx.x >> 5;
    v = warpSum(v);
    if (lane == 0) sm[w] = v;
    __syncthreads();
    if (threadIdx.x == 0){
        float s = 0.f;
        for (int i = 0; i < 8; i++) s += sm[i];
        sm[8] = s;
    }
    __syncthreads();
    return sm[8];
}
__device__ __forceinline__ float blockMax(float v, float* sm){
    int lane = threadIdx.x & 31, w = threadIdx.x >> 5;
    v = warpMax(v);
    if (lane == 0) sm[w] = v;
    __syncthreads();
    if (threadIdx.x == 0){
        float s = sm[0];
        for (int i = 1; i < 8; i++) s = fmaxf(s, sm[i]);
        sm[8] = s;
    }
    __syncthreads();
    return sm[8];
}
__device__ __forceinline__ float gelu_exact(float v){
    return 0.5f * v * (1.0f + erff(v * 0.7071067811865475f));
}
__device__ __forceinline__ void hilo_pack(float x, float y, unsigned& uh, unsigned& ul){
    __half hx = __float2half_rn(x);
    __half hy = __float2half_rn(y);
    __half lx = __float2half_rn(x - __half2float(hx));
    __half ly = __float2half_rn(y - __half2float(hy));
    __half2 th = __halves2half2(hx, hy);
    __half2 tl = __halves2half2(lx, ly);
    uh = *reinterpret_cast<unsigned*>(&th);
    ul = *reinterpret_cast<unsigned*>(&tl);
}
__device__ __forceinline__ void mma_f16(float* d, const unsigned* a, const unsigned* b){
    asm volatile(
        "mma.sync.aligned.m16n8k16.row.col.f32.f16.f16.f32 "
        "{%0,%1,%2,%3}, {%4,%5,%6,%7}, {%8,%9}, {%0,%1,%2,%3};\n"
        : "+f"(d[0]), "+f"(d[1]), "+f"(d[2]), "+f"(d[3])
        : "r"(a[0]), "r"(a[1]), "r"(a[2]), "r"(a[3]), "r"(b[0]), "r"(b[1]));
}

// ---------------- operand converters ----------------
__global__ void cvt_hl_vec4(const float* __restrict__ src,
                            unsigned* __restrict__ dh, unsigned* __restrict__ dl, int n4){
    int i = blockIdx.x * blockDim.x + threadIdx.x;
    if (i < n4){
        float4 v = ((const float4*)src)[i];
        unsigned h0,l0,h1,l1;
        hilo_pack(v.x, v.y, h0, l0);
        hilo_pack(v.z, v.w, h1, l1);
        ((uint2*)dh)[i] = make_uint2(h0, h1);
        ((uint2*)dl)[i] = make_uint2(l0, l1);
    }
}
// weight k-pair packing: out[(l*(K/2)+kp)*N + n] = half2(B[l][2kp][n], B[l][2kp+1][n])
__global__ void cvt_kpair(const float* __restrict__ B,
                          unsigned* __restrict__ BH, unsigned* __restrict__ BL,
                          int K, int N, int L){
    long idx = (long)blockIdx.x * blockDim.x + threadIdx.x;
    long total = (long)L * (K/2) * N;
    if (idx < total){
        int n  = idx % N;
        long t = idx / N;
        int kp = t % (K/2);
        int l  = t / (K/2);
        const float* Bl = B + (size_t)l * K * N;
        unsigned h, lo;
        hilo_pack(Bl[(size_t)(2*kp) * N + n], Bl[(size_t)(2*kp+1) * N + n], h, lo);
        BH[idx] = h; BL[idx] = lo;
    }
}

// =============================================================
// 3xFP16 tensor-core GEMM, pre-converted operands.
// 128x128x32 CTA tile, 8 warps (64x32 each).
// MODE 0: C = A@B ; MODE 2: gelu(A@B+bias) -> half hi/lo out
// MODE 3: C += A@B + bias ; MODE 4: image-gather patch embed
// =============================================================
template<int MODE>
__global__ __launch_bounds__(256)
void tgemm(const unsigned* __restrict__ AH, const unsigned* __restrict__ AL, int lda,
           const unsigned* __restrict__ BH, const unsigned* __restrict__ BL,
           float* __restrict__ C, int ldc,
           int M, int N, int K,
           const float* __restrict__ bias,
           unsigned* __restrict__ outH, unsigned* __restrict__ outL)
{
    __shared__ unsigned sAh[2048], sAl[2048], sBh[2048], sBl[2048];

    const int tx   = threadIdx.x;
    const int wid  = tx >> 5;
    const int lane = tx & 31;
    const int warp_m = wid >> 2;
    const int warp_n = wid & 3;
    const int bm = blockIdx.y * 128;
    const int bn = blockIdx.x * 128;

    const int a_m  = tx >> 3;        // 0..31
    const int a_kv = tx & 7;         // k quad
    const int b_q  = tx & 31;        // n quad

    float acc[4][4][4] = {};

    uint2 arH[4], arL[4];
    uint4 brH[2], brL[2];

    auto load_stage = [&](int k0){
        #pragma unroll
        for (int it = 0; it < 4; it++){
            int m = a_m + 32*it;
            size_t off;
            if (MODE == 4){
                int mg = bm + m;
                int gb = mg / (NP*NP);
                int p  = mg % (NP*NP);
                int gi = p / NP, gj = p % NP;
                int k  = k0 + a_kv*4;
                int c  = k >> 10;
                int rem = k & 1023;
                int hh = rem >> 5, ww = rem & 31;
                off = ((size_t)(gb*3 + c) * IMG + (gi*PS + hh)) * IMG + gj*PS + ww;
            } else {
                off = (size_t)(bm + m) * lda + k0 + a_kv*4;
            }
            arH[it] = *(const uint2*)(AH + (off >> 1));
            arL[it] = *(const uint2*)(AL + (off >> 1));
        }
        #pragma unroll
        for (int it = 0; it < 2; it++){
            int kp = (k0 >> 1) + wid + (it << 3);
            brH[it] = *(const uint4*)(BH + (size_t)kp * N + bn + b_q*4);   // FIX: + bn
            brL[it] = *(const uint4*)(BL + (size_t)kp * N + bn + b_q*4);   // FIX: + bn
        }
    };

    auto store_stage = [&](){
        #pragma unroll
        for (int it = 0; it < 4; it++){
            int m   = a_m + 32*it;
            int ks  = a_kv >> 2;
            int kp0 = ((a_kv & 3) << 2) >> 1;    // 0,2,4,6
            int g   = (m >> 4)*2 + ks;
            int reg = ((m & 15) >> 3) + ((kp0 & 4) ? 2 : 0);
            int lane0 = (m & 7)*4 + (kp0 & 3);
            int base = g*128 + reg*32;
            sAh[base + lane0]     = arH[it].x;  sAl[base + lane0]     = arL[it].x;
            sAh[base + lane0 + 1] = arH[it].y;  sAl[base + lane0 + 1] = arL[it].y;
        }
        #pragma unroll
        for (int it = 0; it < 2; it++){
            int reg = (wid >> 2) & 1;
            int w3  = wid & 3;
            const unsigned* uh = (const unsigned*)&brH[it];
            const unsigned* ul = (const unsigned*)&brL[it];
            #pragma unroll
            for (int j = 0; j < 4; j++){
                int n  = b_q*4 + j;
                int g  = (n >> 3)*2 + it;
                int s  = (n >> 3) & 7;
                int ln = (((n & 7)*4 + w3) ^ s);
                sBh[g*64 + reg*32 + ln] = uh[j];
                sBl[g*64 + reg*32 + ln] = ul[j];
            }
        }
    };

    load_stage(0);

    for (int k0 = 0; k0 < K; k0 += 32){
        store_stage();
        __syncthreads();
        if (k0 + 32 < K) load_stage(k0 + 32);

        #pragma unroll
        for (int ks = 0; ks < 2; ks++){
            unsigned ah[4][4], al[4][4];
            unsigned bh[4][2], bl[4][2];
            #pragma unroll
            for (int mt = 0; mt < 4; mt++){
                int g = (warp_m*4 + mt)*2 + ks;
                int base = g*128;
                #pragma unroll
                for (int r = 0; r < 4; r++){
                    ah[mt][r] = sAh[base + r*32 + lane];
                    al[mt][r] = sAl[base + r*32 + lane];
                }
            }
            #pragma unroll
            for (int nt = 0; nt < 4; nt++){
                int ntile = warp_n*4 + nt;
                int g  = ntile*2 + ks;
                int ln = lane ^ (ntile & 7);
                bh[nt][0] = sBh[g*64 + ln];   bh[nt][1] = sBh[g*64 + 32 + ln];
                bl[nt][0] = sBl[g*64 + ln];   bl[nt][1] = sBl[g*64 + 32 + ln];
            }
            #pragma unroll
            for (int mt = 0; mt < 4; mt++)
                #pragma unroll
                for (int nt = 0; nt < 4; nt++){
                    mma_f16(acc[mt][nt], al[mt], bh[nt]);
                    mma_f16(acc[mt][nt], ah[mt], bl[nt]);
                    mma_f16(acc[mt][nt], ah[mt], bh[nt]);
                }
        }
        __syncthreads();
    }

    // ---- epilogue ----
    #pragma unroll
    for (int mt = 0; mt < 4; mt++){
        int r0 = bm + warp_m*64 + mt*16 + (lane >> 2);
        #pragma unroll
        for (int half = 0; half < 2; half++){
            int row = r0 + half*8;
            int orow = row;
            int tpos = 0;
            if (MODE == 4){
                int b = row / (NP*NP);
                int p = row % (NP*NP);
                tpos = p + 1;
                orow = b * NTOK + tpos;
            }
            #pragma unroll
            for (int nt = 0; nt < 4; nt++){
                int c0 = bn + warp_n*32 + nt*8 + ((lane & 3) << 1);
                float v0 = acc[mt][nt][half*2 + 0];
                float v1 = acc[mt][nt][half*2 + 1];
                if (MODE >= 2){ v0 += bias[c0]; v1 += bias[c0+1]; }
                if (MODE == 2){
                    v0 = gelu_exact(v0); v1 = gelu_exact(v1);
                    unsigned uh, ul;
                    hilo_pack(v0, v1, uh, ul);
                    size_t oi = ((size_t)orow * ldc + c0) >> 1;
                    outH[oi] = uh; outL[oi] = ul;
                    continue;
                }
                if (MODE == 4){
                    float fac = expf(-(float)c0 * 0.03597789207803285f);
                    float ang = (float)tpos * fac;
                    float s, c;
                    sincosf(ang, &s, &c);
                    v0 += s; v1 += c;
                }
                float* cp = C + (size_t)orow * ldc + c0;
                if (MODE == 3){
                    float2 old = *(const float2*)cp;
                    v0 += old.x; v1 += old.y;
                }
                float2 o; o.x = v0; o.y = v1;
                *(float2*)cp = o;
            }
        }
    }
}

// ---------------- SIMT GEMM (small head GEMM: +bias) ----------------
__global__ __launch_bounds__(256)
void gemm64(const float* __restrict__ A, int lda,
            const float* __restrict__ B, int ldb,
            float* __restrict__ C, int ldc,
            int M, int N, int K,
            const float* __restrict__ bias)
{
    __shared__ float As[16][64];
    __shared__ float Bs[16][68];

    const int tx = threadIdx.x;
    const int bm = blockIdx.y * 64;
    const int bn = blockIdx.x * 64;

    const int am  = tx >> 2;
    const int ak  = (tx & 3) << 2;
    const int bk  = tx >> 4;
    const int bnn = (tx & 15) << 2;
    const int tm  = (tx >> 4) << 2;
    const int tn  = (tx & 15) << 2;

    const int arow = bm + am;

    float acc[4][4];
    #pragma unroll
    for (int i=0;i<4;i++)
        #pragma unroll
        for (int j=0;j<4;j++) acc[i][j] = 0.f;

    for (int k0 = 0; k0 < K; k0 += 16){
        float4 av = make_float4(0.f,0.f,0.f,0.f);
        if (arow < M)
            av = *(const float4*)(A + (size_t)arow * lda + k0 + ak);
        As[ak+0][am] = av.x; As[ak+1][am] = av.y;
        As[ak+2][am] = av.z; As[ak+3][am] = av.w;

        float4 bv = make_float4(0.f,0.f,0.f,0.f);
        if (bn + bnn < N)
            bv = *(const float4*)(B + (size_t)(k0 + bk) * ldb + bn + bnn);
        *(float4*)&Bs[bk][bnn] = bv;

        __syncthreads();
        #pragma unroll
        for (int kk = 0; kk < 16; kk++){
            float4 a = *(const float4*)&As[kk][tm];
            float4 b = *(const float4*)&Bs[kk][tn];
            acc[0][0] += a.x*b.x; acc[0][1] += a.x*b.y; acc[0][2] += a.x*b.z; acc[0][3] += a.x*b.w;
            acc[1][0] += a.y*b.x; acc[1][1] += a.y*b.y; acc[1][2] += a.y*b.z; acc[1][3] += a.y*b.w;
            acc[2][0] += a.z*b.x; acc[2][1] += a.z*b.y; acc[2][2] += a.z*b.z; acc[2][3] += a.z*b.w;
            acc[3][0] += a.w*b.x; acc[3][1] += a.w*b.y; acc[3][2] += a.w*b.z; acc[3][3] += a.w*b.w;
        }
        __syncthreads();
    }

    #pragma unroll
    for (int i=0;i<4;i++){
        int row = bm + tm + i;
        if (row >= M) continue;
        #pragma unroll
        for (int j=0;j<4;j++){
            int col = bn + tn + j;
            if (col >= N) continue;
            C[(size_t)row * ldc + col] = acc[i][j] + bias[col];
        }
    }
}

// ---------------- CLS token init ----------------
__global__ void cls_init_kernel(const float* __restrict__ cls, float* __restrict__ x){
    int b = blockIdx.x, c = threadIdx.x;
    x[(size_t)b * NTOK * HID + c] = cls[c] + ((c & 1) ? 1.0f : 0.0f);
}

// ---------------- CSR build ----------------
__global__ void build_csr_kernel(const int* __restrict__ edge_index, int E){
    __shared__ int s_src[EMAX], s_dst[EMAX], cnt[NTOK];
    int t = threadIdx.x;
    for (int e = t; e < E; e += 64){
        s_src[e] = edge_index[e];
        s_dst[e] = edge_index[E + e];
    }
    __syncthreads();
    if (t < NTOK){
        int c = 1;
        for (int e = 0; e < E; e++) if (s_dst[e] == t) c++;
        cnt[t] = c;
    }
    __syncthreads();
    if (t == 0){
        int s = 0;
        for (int n = 0; n < NTOK; n++){ g_csr_ptr[n] = s; s += cnt[n]; }
        g_csr_ptr[NTOK] = s;
    }
    __syncthreads();
    if (t < NTOK){
        int pos = g_csr_ptr[t];
        for (int e = 0; e < E; e++) if (s_dst[e] == t) g_csr_src[pos++] = s_src[e];
        g_csr_src[pos++] = t;
    }
}

// ---------------- LayerNorm (warp-per-row) -> hi/lo fp16 ----------------
__global__ __launch_bounds__(256)
void ln_kernel(const float* __restrict__ x,
               unsigned* __restrict__ yH, unsigned* __restrict__ yL,
               const float* __restrict__ g, const float* __restrict__ b){
    int row  = blockIdx.x * 8 + (threadIdx.x >> 5);
    int lane = threadIdx.x & 31;
    const float* xr = x + (size_t)row * HID;
    float4 v0 = *(const float4*)(xr + lane*4);
    float4 v1 = *(const float4*)(xr + 128 + lane*4);
    float s = v0.x+v0.y+v0.z+v0.w + v1.x+v1.y+v1.z+v1.w;
    float mu = warpSum(s) * (1.0f / HID);
    float d0x=v0.x-mu, d0y=v0.y-mu, d0z=v0.z-mu, d0w=v0.w-mu;
    float d1x=v1.x-mu, d1y=v1.y-mu, d1z=v1.z-mu, d1w=v1.w-mu;
    float q = d0x*d0x+d0y*d0y+d0z*d0z+d0w*d0w + d1x*d1x+d1y*d1y+d1z*d1z+d1w*d1w;
    float var = warpSum(q) * (1.0f / HID);
    float inv = rsqrtf(var + 1e-5f);
    float4 g0 = *(const float4*)(g + lane*4);
    float4 g1 = *(const float4*)(g + 128 + lane*4);
    float4 b0 = *(const float4*)(b + lane*4);
    float4 b1 = *(const float4*)(b + 128 + lane*4);
    float o0x = d0x*inv*g0.x + b0.x, o0y = d0y*inv*g0.y + b0.y;
    float o0z = d0z*inv*g0.z + b0.z, o0w = d0w*inv*g0.w + b0.w;
    float o1x = d1x*inv*g1.x + b1.x, o1y = d1y*inv*g1.y + b1.y;
    float o1z = d1z*inv*g1.z + b1.z, o1w = d1w*inv*g1.w + b1.w;
    unsigned h0,l0,h1,l1,h2,l2,h3,l3;
    hilo_pack(o0x,o0y,h0,l0); hilo_pack(o0z,o0w,h1,l1);
    hilo_pack(o1x,o1y,h2,l2); hilo_pack(o1z,o1w,h3,l3);
    size_t u0 = ((size_t)row * HID + lane*4) >> 1;
    size_t u1 = ((size_t)row * HID + 128 + lane*4) >> 1;
    *(uint2*)(yH + u0) = make_uint2(h0,h1);
    *(uint2*)(yL + u0) = make_uint2(l0,l1);
    *(uint2*)(yH + u1) = make_uint2(h2,h3);
    *(uint2*)(yL + u1) = make_uint2(l2,l3);
}

// ---------------- per-head attention logit dots ----------------
__global__ __launch_bounds__(256)
void att_logits_kernel(const float* __restrict__ h,
                       const float* __restrict__ att_src,
                       const float* __restrict__ att_dst,
                       float* __restrict__ als, float* __restrict__ ald){
    int row = blockIdx.x;
    int w = threadIdx.x >> 5, lane = threadIdx.x & 31;
    float hv = h[(size_t)row * HID + w * DH + lane];
    float vs = warpSum(hv * att_src[w * DH + lane]);
    float vd = warpSum(hv * att_dst[w * DH + lane]);
    if (lane == 0){
        als[row * HEADS + w] = vs;
        ald[row * HEADS + w] = vd;
    }
}

// ---------------- edge softmax ----------------
__global__ __launch_bounds__(256)
void alpha_kernel(const float* __restrict__ als, const float* __restrict__ ald,
                  float* __restrict__ alpha, int E_tot){
    __shared__ float earr[HEADS][64];
    int b = blockIdx.x / NTOK, n = blockIdx.x % NTOK;
    int head = threadIdx.x >> 5, lane = threadIdx.x & 31;
    int base = g_csr_ptr[n], deg = g_csr_ptr[n+1] - base;
    float aldv = ald[(size_t)(b * NTOK + n) * HEADS + head];
    float m = -1e30f;
    for (int p = lane; p < deg; p += 32){
        int src = g_csr_src[base + p];
        float e = als[(size_t)(b * NTOK + src) * HEADS + head] + aldv;
        e = (e > 0.f) ? e : 0.2f * e;
        earr[head][p] = e;
        m = fmaxf(m, e);
    }
    m = warpMax(m);
    float s = 0.f;
    for (int p = lane; p < deg; p += 32){
        float ex = expf(earr[head][p] - m);
        earr[head][p] = ex;
        s += ex;
    }
    s = warpSum(s);
    float inv = 1.0f / (s + 1e-16f);
    for (int p = lane; p < deg; p += 32)
        alpha[((size_t)b * E_tot + base + p) * HEADS + head] = earr[head][p] * inv;
}

// ---------------- GAT aggregation + bias + residual ----------------
__global__ __launch_bounds__(256)
void gat_out_kernel(const float* __restrict__ h, const float* __restrict__ alpha,
                    const float* __restrict__ bias, float* __restrict__ x, int E_tot){
    int b = blockIdx.x / NTOK, n = blockIdx.x % NTOK;
    int c = threadIdx.x, head = c >> 5;
    int base = g_csr_ptr[n], deg = g_csr_ptr[n+1] - base;
    float acc = 0.f;
    for (int p = 0; p < deg; p++){
        int src = g_csr_src[base + p];
        float a = alpha[((size_t)b * E_tot + base + p) * HEADS + head];
        acc += a * h[(size_t)(b * NTOK + src) * HID + c];
    }
    size_t idx = (size_t)(b * NTOK + n) * HID + c;
    x[idx] += acc + bias[c];
}

// ---------------- final row softmax ----------------
__global__ __launch_bounds__(256)
void softmax_kernel(const float* __restrict__ logits, float* __restrict__ out){
    __shared__ float sm[9];
    int row = blockIdx.x, t = threadIdx.x;
    float v[4];
    float m = -1e30f;
    #pragma unroll
    for (int k = 0; k < 4; k++){
        int c = t + k * 256;
        v[k] = (c < OUTD) ? logits[(size_t)row * OUTD + c] : -1e30f;
        m = fmaxf(m, v[k]);
    }
    m = blockMax(m, sm);
    float s = 0.f;
    #pragma unroll
    for (int k = 0; k < 4; k++){
        v[k] = expf(v[k] - m);
        int c = t + k * 256;
        if (c < OUTD) s += v[k];
    }
    s = blockSum(s, sm);
    float inv = 1.0f / s;
    #pragma unroll
    for (int k = 0; k < 4; k++){
        int c = t + k * 256;
        if (c < OUTD) out[(size_t)row * OUTD + c] = v[k] * inv;
    }
}

// ---------------- host launch ----------------
extern "C" void kernel_launch(void* const* d_in, const int* in_sizes, int n_in,
                              void* d_out, int out_size)
{
    const float* images  = (const float*)d_in[0];
    const int*   eidx    = (const int*)  d_in[1];
    const float* Wmap    = (const float*)d_in[2];
    const float* bmap    = (const float*)d_in[3];
    const float* cls_tok = (const float*)d_in[4];
    const float* Wgat    = (const float*)d_in[5];
    const float* att_src = (const float*)d_in[6];
    const float* att_dst = (const float*)d_in[7];
    const float* bgat    = (const float*)d_in[8];
    const float* ln1_g   = (const float*)d_in[9];
    const float* ln1_b   = (const float*)d_in[10];
    const float* ln2_g   = (const float*)d_in[11];
    const float* ln2_b   = (const float*)d_in[12];
    const float* W1      = (const float*)d_in[13];
    const float* b1      = (const float*)d_in[14];
    const float* W2      = (const float*)d_in[15];
    const float* b2      = (const float*)d_in[16];
    const float* Wout    = (const float*)d_in[17];
    const float* bout    = (const float*)d_in[18];

    int E = in_sizes[1] / 2;
    int E_tot = E + NTOK;

    float *x, *h, *als, *ald, *alpha, *logits;
    unsigned *imgH, *imgL, *yH, *yL, *mlpH, *mlpL;
    unsigned *WmapH, *WmapL, *WgatH, *WgatL, *W1H, *W1L, *W2H, *W2L;
    cudaGetSymbolAddress((void**)&x,      g_x);
    cudaGetSymbolAddress((void**)&h,      g_h);
    cudaGetSymbolAddress((void**)&als,    g_als);
    cudaGetSymbolAddress((void**)&ald,    g_ald);
    cudaGetSymbolAddress((void**)&alpha,  g_alpha);
    cudaGetSymbolAddress((void**)&logits, g_logits);
    cudaGetSymbolAddress((void**)&imgH,   g_imgH);
    cudaGetSymbolAddress((void**)&imgL,   g_imgL);
    cudaGetSymbolAddress((void**)&yH,     g_yH);
    cudaGetSymbolAddress((void**)&yL,     g_yL);
    cudaGetSymbolAddress((void**)&mlpH,   g_mlpH);
    cudaGetSymbolAddress((void**)&mlpL,   g_mlpL);
    cudaGetSymbolAddress((void**)&WmapH,  g_WmapH);
    cudaGetSymbolAddress((void**)&WmapL,  g_WmapL);
    cudaGetSymbolAddress((void**)&WgatH,  g_WgatH);
    cudaGetSymbolAddress((void**)&WgatL,  g_WgatL);
    cudaGetSymbolAddress((void**)&W1H,    g_W1H);
    cudaGetSymbolAddress((void**)&W1L,    g_W1L);
    cudaGetSymbolAddress((void**)&W2H,    g_W2H);
    cudaGetSymbolAddress((void**)&W2L,    g_W2L);

    // ---- operand conversion ----
    cvt_hl_vec4<<<(IMGELEM/4 + 255)/256, 256>>>(images, imgH, imgL, IMGELEM/4);
    {
        long t;
        t = (long)1*(INPUTD/2)*HID;
        cvt_kpair<<<(unsigned)((t + 255)/256), 256>>>(Wmap, WmapH, WmapL, INPUTD, HID, 1);
        t = (long)4*(HID/2)*HID;
        cvt_kpair<<<(unsigned)((t + 255)/256), 256>>>(Wgat, WgatH, WgatL, HID, HID, 4);
        t = (long)4*(HID/2)*MLPD;
        cvt_kpair<<<(unsigned)((t + 255)/256), 256>>>(W1, W1H, W1L, HID, MLPD, 4);
        t = (long)4*(MLPD/2)*HID;
        cvt_kpair<<<(unsigned)((t + 255)/256), 256>>>(W2, W2H, W2L, MLPD, HID, 4);
    }

    // patch embed
    tgemm<4><<<dim3(HID/128, PROWS/128), 256>>>(imgH, imgL, 0, WmapH, WmapL,
                                                x, HID, PROWS, HID, INPUTD, bmap,
                                                nullptr, nullptr);
    cls_init_kernel<<<BATCH, HID>>>(cls_tok, x);
    build_csr_kernel<<<1, 64>>>(eidx, E);

    for (int l = 0; l < 4; l++){
        ln_kernel<<<ROWS/8, 256>>>(x, yH, yL, ln1_g + l*HID, ln1_b + l*HID);
        tgemm<0><<<dim3(HID/128, ROWS/128), 256>>>(yH, yL, HID,
                                                   WgatH + (size_t)l*(HID/2)*HID,
                                                   WgatL + (size_t)l*(HID/2)*HID,
                                                   h, HID, ROWS, HID, HID, nullptr,
                                                   nullptr, nullptr);
        att_logits_kernel<<<ROWS, 256>>>(h, att_src + l*HID, att_dst + l*HID, als, ald);
        alpha_kernel<<<ROWS, 256>>>(als, ald, alpha, E_tot);
        gat_out_kernel<<<ROWS, 256>>>(h, alpha, bgat + l*HID, x, E_tot);

        ln_kernel<<<ROWS/8, 256>>>(x, yH, yL, ln2_g + l*HID, ln2_b + l*HID);
        tgemm<2><<<dim3(MLPD/128, ROWS/128), 256>>>(yH, yL, HID,
                                                    W1H + (size_t)l*(HID/2)*MLPD,
                                                    W1L + (size_t)l*(HID/2)*MLPD,
                                                    nullptr, MLPD, ROWS, MLPD, HID, b1 + l*MLPD,
                                                    mlpH, mlpL);
        tgemm<3><<<dim3(HID/128, ROWS/128), 256>>>(mlpH, mlpL, MLPD,
                                                   W2H + (size_t)l*(MLPD/2)*HID,
                                                   W2L + (size_t)l*(MLPD/2)*HID,
                                                   x, HID, ROWS, HID, MLPD, b2 + l*HID,
                                                   nullptr, nullptr);
    }

    gemm64<<<dim3((OUTD+63)/64, BATCH/64), 256>>>(x, NTOK*HID, Wout, OUTD,
                                                  logits, OUTD, BATCH, OUTD, HID, bout);
    softmax_kernel<<<BATCH, 256>>>(logits, (float*)d_out);
    (void)n_in; (void)out_size;
}

// round 9
// speedup vs baseline: 1.1014x; 1.1014x over previous
#include <cuda_runtime.h>
#include <cuda_fp16.h>
#include <cuda_bf16.h>
#include <cstdint>
#include <cstddef>

// ---------------- problem constants ----------------
#define BATCH   256
#define NTOK    50
#define NP      7
#define HID     256
#define HEADS   8
#define DH      32
#define MLPD    1024
#define OUTD    1000
#define PS      32
#define IMG     224
#define INPUTD  3072
#define ROWS    (BATCH*NTOK)      // 12800
#define PROWS   (BATCH*NP*NP)     // 12544
#define EMAX    512

// ---------------- device scratch ----------------
__device__ float g_x[ROWS*HID];
__device__ float g_y[ROWS*HID];
__device__ float g_h[ROWS*HID];
__device__ float g_mlp[ROWS*MLPD];
__device__ float g_als[ROWS*HEADS];
__device__ float g_ald[ROWS*HEADS];
__device__ float g_alpha[(size_t)BATCH*EMAX*HEADS];
__device__ float g_logits[BATCH*OUTD];
__device__ int   g_csr_ptr[NTOK+1];
__device__ int   g_csr_src[1024];

// ---------------- helpers ----------------
__device__ __forceinline__ float warpSum(float v){
    #pragma unroll
    for (int o=16;o;o>>=1) v += __shfl_xor_sync(0xffffffffu, v, o);
    return v;
}
__device__ __forceinline__ float warpMax(float v){
    #pragma unroll
    for (int o=16;o;o>>=1) v = fmaxf(v, __shfl_xor_sync(0xffffffffu, v, o));
    return v;
}
__device__ __forceinline__ float blockSum(float v, float* sm){
    int lane = threadIdx.x & 31, w = threadIdx.x >> 5;
    v = warpSum(v);
    if (lane == 0) sm[w] = v;
    __syncthreads();
    if (threadIdx.x == 0){
        float s = 0.f;
        for (int i = 0; i < 8; i++) s += sm[i];
        sm[8] = s;
    }
    __syncthreads();
    return sm[8];
}
__device__ __forceinline__ float blockMax(float v, float* sm){
    int lane = threadIdx.x & 31, w = threadIdx.x >> 5;
    v = warpMax(v);
    if (lane == 0) sm[w] = v;
    __syncthreads();
    if (threadIdx.x == 0){
        float s = sm[0];
        for (int i = 1; i < 8; i++) s = fmaxf(s, sm[i]);
        sm[8] = s;
    }
    __syncthreads();
    return sm[8];
}
__device__ __forceinline__ float gelu_exact(float v){
    return 0.5f * v * (1.0f + erff(v * 0.7071067811865475f));
}
// pack two fp32 into half2-as-u32 (hi parts) and (lo parts)
__device__ __forceinline__ void hilo_pack(float x, float y, unsigned& uh, unsigned& ul){
    __half hx = __float2half_rn(x);
    __half hy = __float2half_rn(y);
    __half lx = __float2half_rn(x - __half2float(hx));
    __half ly = __float2half_rn(y - __half2float(hy));
    __half2 th = __halves2half2(hx, hy);
    __half2 tl = __halves2half2(lx, ly);
    uh = *reinterpret_cast<unsigned*>(&th);
    ul = *reinterpret_cast<unsigned*>(&tl);
}
__device__ __forceinline__ void mma_f16(float* d, const unsigned* a, const unsigned* b){
    asm volatile(
        "mma.sync.aligned.m16n8k16.row.col.f32.f16.f16.f32 "
        "{%0,%1,%2,%3}, {%4,%5,%6,%7}, {%8,%9}, {%0,%1,%2,%3};\n"
        : "+f"(d[0]), "+f"(d[1]), "+f"(d[2]), "+f"(d[3])
        : "r"(a[0]), "r"(a[1]), "r"(a[2]), "r"(a[3]), "r"(b[0]), "r"(b[1]));
}

// =============================================================
// 3xFP16 tensor-core GEMM: 128x128x32 CTA tile, 8 warps (64x32 each)
// Double-buffered smem stages (64KB dynamic): 1 barrier per k-tile.
// MODE 0: C = A@B
// MODE 2: C = gelu(A@B + bias)
// MODE 3: C = C + A@B + bias
// MODE 4: patch-embed (A gathered from images, +bias+posemb, row remap)
// Requires: M%128==0, N%128==0, K%32==0.
// =============================================================
template<int MODE>
__global__ __launch_bounds__(256)
void tgemm(const float* __restrict__ A, int lda,
           const float* __restrict__ B, int ldb,
           float* __restrict__ C, int ldc,
           int M, int N, int K,
           const float* __restrict__ bias)
{
    // per stage (8192 u32): sAh[2048] sAl[2048] sBh[2048] sBl[2048]
    extern __shared__ unsigned dsm[];

    const int tx   = threadIdx.x;
    const int wid  = tx >> 5;
    const int lane = tx & 31;
    const int warp_m = wid >> 2;     // 0..1
    const int warp_n = wid & 3;      // 0..3
    const int bm = blockIdx.y * 128;
    const int bn = blockIdx.x * 128;

    // A-loader coords: 32 m-rows per slab, 8 threads cover 32 k (float4 each)
    const int a_m  = tx >> 3;        // 0..31
    const int a_kv = tx & 7;         // k quad: k = a_kv*4
    // B-loader coords: thread loads rows k=2*wid+{0,1}(+16*it) at n-quad q
    const int b_q  = tx & 31;        // n quad (4 n each)

    float acc[4][4][4] = {};

    float4 ar[4];          // A rows a_m+32*it, k quad
    float4 br0[2], br1[2]; // B rows pair (k, k+1), it=0,1

    auto load_stage = [&](int k0){
        #pragma unroll
        for (int it = 0; it < 4; it++){
            int m = a_m + 32*it;
            if (MODE == 4){
                int mg = bm + m;
                int gb = mg / (NP*NP);
                int p  = mg % (NP*NP);
                int gi = p / NP, gj = p % NP;
                int k  = k0 + a_kv*4;
                int c  = k >> 10;
                int rem = k & 1023;
                int hh = rem >> 5, ww = rem & 31;
                size_t off = ((size_t)(gb*3 + c) * IMG + (gi*PS + hh)) * IMG + gj*PS + ww;
                ar[it] = *(const float4*)(A + off);
            } else {
                ar[it] = *(const float4*)(A + (size_t)(bm + m) * lda + k0 + a_kv*4);
            }
        }
        #pragma unroll
        for (int it = 0; it < 2; it++){
            int krow = (wid << 1) + (it << 4);
            br0[it] = *(const float4*)(B + (size_t)(k0 + krow    ) * ldb + bn + b_q*4);
            br1[it] = *(const float4*)(B + (size_t)(k0 + krow + 1) * ldb + bn + b_q*4);
        }
    };

    auto store_stage = [&](int buf){
        unsigned* sAh = dsm + buf*8192;
        unsigned* sAl = sAh + 2048;
        unsigned* sBh = sAh + 4096;
        unsigned* sBl = sAh + 6144;
        // ---- A ----
        #pragma unroll
        for (int it = 0; it < 4; it++){
            int m   = a_m + 32*it;
            int ks  = a_kv >> 2;                 // 0/1
            int c   = (a_kv & 3) << 2;           // kk base within k16: 0,4,8,12
            int kp0 = c >> 1;                    // 0,2,4,6
            int g   = (m >> 4)*2 + ks;
            int reg = ((m & 15) >> 3) + ((kp0 & 4) ? 2 : 0);
            int lane0 = (m & 7)*4 + (kp0 & 3);
            int base = g*128 + reg*32;
            unsigned uh, ul;
            hilo_pack(ar[it].x, ar[it].y, uh, ul);
            sAh[base + lane0]     = uh;  sAl[base + lane0]     = ul;
            hilo_pack(ar[it].z, ar[it].w, uh, ul);
            sAh[base + lane0 + 1] = uh;  sAl[base + lane0 + 1] = ul;
        }
        // ---- B ----
        #pragma unroll
        for (int it = 0; it < 2; it++){
            int reg = (wid >> 2) & 1;
            int w3  = wid & 3;
            const float* r0 = (const float*)&br0[it];
            const float* r1 = (const float*)&br1[it];
            #pragma unroll
            for (int j = 0; j < 4; j++){
                int n  = b_q*4 + j;
                int g  = (n >> 3)*2 + it;
                int s  = (n >> 3) & 7;
                int ln = (((n & 7)*4 + w3) ^ s);
                unsigned uh, ul;
                hilo_pack(r0[j], r1[j], uh, ul);
                sBh[g*64 + reg*32 + ln] = uh;
                sBl[g*64 + reg*32 + ln] = ul;
            }
        }
    };

    auto compute = [&](int buf){
        unsigned* sAh = dsm + buf*8192;
        unsigned* sAl = sAh + 2048;
        unsigned* sBh = sAh + 4096;
        unsigned* sBl = sAh + 6144;
        #pragma unroll
        for (int ks = 0; ks < 2; ks++){
            unsigned ah[4][4], al[4][4];
            unsigned bh[4][2], bl[4][2];
            #pragma unroll
            for (int mt = 0; mt < 4; mt++){
                int g = (warp_m*4 + mt)*2 + ks;
                int base = g*128;
                #pragma unroll
                for (int r = 0; r < 4; r++){
                    ah[mt][r] = sAh[base + r*32 + lane];
                    al[mt][r] = sAl[base + r*32 + lane];
                }
            }
            #pragma unroll
            for (int nt = 0; nt < 4; nt++){
                int ntile = warp_n*4 + nt;
                int g  = ntile*2 + ks;
                int ln = lane ^ (ntile & 7);
                bh[nt][0] = sBh[g*64 + ln];   bh[nt][1] = sBh[g*64 + 32 + ln];
                bl[nt][0] = sBl[g*64 + ln];   bl[nt][1] = sBl[g*64 + 32 + ln];
            }
            #pragma unroll
            for (int mt = 0; mt < 4; mt++)
                #pragma unroll
                for (int nt = 0; nt < 4; nt++){
                    mma_f16(acc[mt][nt], al[mt], bh[nt]);
                    mma_f16(acc[mt][nt], ah[mt], bl[nt]);
                    mma_f16(acc[mt][nt], ah[mt], bh[nt]);
                }
        }
    };

    load_stage(0);
    store_stage(0);
    __syncthreads();

    const int NS = K / 32;
    for (int kt = 0; kt < NS; kt++){
        if (kt + 1 < NS) load_stage((kt + 1) * 32);
        compute(kt & 1);
        if (kt + 1 < NS){
            store_stage((kt + 1) & 1);
            __syncthreads();
        }
    }

    // ---- epilogue ----
    #pragma unroll
    for (int mt = 0; mt < 4; mt++){
        int r0 = bm + warp_m*64 + mt*16 + (lane >> 2);
        #pragma unroll
        for (int half = 0; half < 2; half++){
            int row = r0 + half*8;
            int orow = row;
            int tpos = 0;
            if (MODE == 4){
                int b = row / (NP*NP);
                int p = row % (NP*NP);
                tpos = p + 1;
                orow = b * NTOK + tpos;
            }
            #pragma unroll
            for (int nt = 0; nt < 4; nt++){
                int c0 = bn + warp_n*32 + nt*8 + ((lane & 3) << 1);
                float v0 = acc[mt][nt][half*2 + 0];
                float v1 = acc[mt][nt][half*2 + 1];
                if (MODE >= 2){ v0 += bias[c0]; v1 += bias[c0+1]; }
                if (MODE == 2){ v0 = gelu_exact(v0); v1 = gelu_exact(v1); }
                if (MODE == 4){
                    float fac = expf(-(float)c0 * 0.03597789207803285f);
                    float ang = (float)tpos * fac;
                    float s, c;
                    sincosf(ang, &s, &c);
                    v0 += s; v1 += c;
                }
                float* cp = C + (size_t)orow * ldc + c0;
                if (MODE == 3){
                    float2 old = *(const float2*)cp;
                    v0 += old.x; v1 += old.y;
                }
                float2 o; o.x = v0; o.y = v1;
                *(float2*)cp = o;
            }
        }
    }
}

// ---------------- SIMT GEMM (small head GEMM: +bias) ----------------
__global__ __launch_bounds__(256)
void gemm64(const float* __restrict__ A, int lda,
            const float* __restrict__ B, int ldb,
            float* __restrict__ C, int ldc,
            int M, int N, int K,
            const float* __restrict__ bias)
{
    __shared__ float As[16][64];
    __shared__ float Bs[16][68];

    const int tx = threadIdx.x;
    const int bm = blockIdx.y * 64;
    const int bn = blockIdx.x * 64;

    const int am  = tx >> 2;
    const int ak  = (tx & 3) << 2;
    const int bk  = tx >> 4;
    const int bnn = (tx & 15) << 2;
    const int tm  = (tx >> 4) << 2;
    const int tn  = (tx & 15) << 2;

    const int arow = bm + am;

    float acc[4][4];
    #pragma unroll
    for (int i=0;i<4;i++)
        #pragma unroll
        for (int j=0;j<4;j++) acc[i][j] = 0.f;

    for (int k0 = 0; k0 < K; k0 += 16){
        float4 av = make_float4(0.f,0.f,0.f,0.f);
        if (arow < M)
            av = *(const float4*)(A + (size_t)arow * lda + k0 + ak);
        As[ak+0][am] = av.x; As[ak+1][am] = av.y;
        As[ak+2][am] = av.z; As[ak+3][am] = av.w;

        float4 bv = make_float4(0.f,0.f,0.f,0.f);
        if (bn + bnn < N)
            bv = *(const float4*)(B + (size_t)(k0 + bk) * ldb + bn + bnn);
        *(float4*)&Bs[bk][bnn] = bv;

        __syncthreads();
        #pragma unroll
        for (int kk = 0; kk < 16; kk++){
            float4 a = *(const float4*)&As[kk][tm];
            float4 b = *(const float4*)&Bs[kk][tn];
            acc[0][0] += a.x*b.x; acc[0][1] += a.x*b.y; acc[0][2] += a.x*b.z; acc[0][3] += a.x*b.w;
            acc[1][0] += a.y*b.x; acc[1][1] += a.y*b.y; acc[1][2] += a.y*b.z; acc[1][3] += a.y*b.w;
            acc[2][0] += a.z*b.x; acc[2][1] += a.z*b.y; acc[2][2] += a.z*b.z; acc[2][3] += a.z*b.w;
            acc[3][0] += a.w*b.x; acc[3][1] += a.w*b.y; acc[3][2] += a.w*b.z; acc[3][3] += a.w*b.w;
        }
        __syncthreads();
    }

    #pragma unroll
    for (int i=0;i<4;i++){
        int row = bm + tm + i;
        if (row >= M) continue;
        #pragma unroll
        for (int j=0;j<4;j++){
            int col = bn + tn + j;
            if (col >= N) continue;
            C[(size_t)row * ldc + col] = acc[i][j] + bias[col];
        }
    }
}

// ---------------- CLS token init ----------------
__global__ void cls_init_kernel(const float* __restrict__ cls, float* __restrict__ x){
    int b = blockIdx.x, c = threadIdx.x;
    x[(size_t)b * NTOK * HID + c] = cls[c] + ((c & 1) ? 1.0f : 0.0f);
}

// ---------------- CSR build ----------------
__global__ void build_csr_kernel(const int* __restrict__ edge_index, int E){
    __shared__ int s_src[EMAX], s_dst[EMAX], cnt[NTOK];
    int t = threadIdx.x;
    for (int e = t; e < E; e += 64){
        s_src[e] = edge_index[e];
        s_dst[e] = edge_index[E + e];
    }
    __syncthreads();
    if (t < NTOK){
        int c = 1;
        for (int e = 0; e < E; e++) if (s_dst[e] == t) c++;
        cnt[t] = c;
    }
    __syncthreads();
    if (t == 0){
        int s = 0;
        for (int n = 0; n < NTOK; n++){ g_csr_ptr[n] = s; s += cnt[n]; }
        g_csr_ptr[NTOK] = s;
    }
    __syncthreads();
    if (t < NTOK){
        int pos = g_csr_ptr[t];
        for (int e = 0; e < E; e++) if (s_dst[e] == t) g_csr_src[pos++] = s_src[e];
        g_csr_src[pos++] = t;
    }
}

// ---------------- LayerNorm (warp-per-row, float out) ----------------
__global__ __launch_bounds__(256)
void ln_kernel(const float* __restrict__ x, float* __restrict__ y,
               const float* __restrict__ g, const float* __restrict__ b){
    int row  = blockIdx.x * 8 + (threadIdx.x >> 5);
    int lane = threadIdx.x & 31;
    const float* xr = x + (size_t)row * HID;
    float4 v0 = *(const float4*)(xr + lane*4);
    float4 v1 = *(const float4*)(xr + 128 + lane*4);
    float s = v0.x+v0.y+v0.z+v0.w + v1.x+v1.y+v1.z+v1.w;
    float mu = warpSum(s) * (1.0f / HID);
    float d0x=v0.x-mu, d0y=v0.y-mu, d0z=v0.z-mu, d0w=v0.w-mu;
    float d1x=v1.x-mu, d1y=v1.y-mu, d1z=v1.z-mu, d1w=v1.w-mu;
    float q = d0x*d0x+d0y*d0y+d0z*d0z+d0w*d0w + d1x*d1x+d1y*d1y+d1z*d1z+d1w*d1w;
    float var = warpSum(q) * (1.0f / HID);
    float inv = rsqrtf(var + 1e-5f);
    float4 g0 = *(const float4*)(g + lane*4);
    float4 g1 = *(const float4*)(g + 128 + lane*4);
    float4 b0 = *(const float4*)(b + lane*4);
    float4 b1 = *(const float4*)(b + 128 + lane*4);
    float* yr = y + (size_t)row * HID;
    float4 o0, o1;
    o0.x = d0x*inv*g0.x + b0.x; o0.y = d0y*inv*g0.y + b0.y;
    o0.z = d0z*inv*g0.z + b0.z; o0.w = d0w*inv*g0.w + b0.w;
    o1.x = d1x*inv*g1.x + b1.x; o1.y = d1y*inv*g1.y + b1.y;
    o1.z = d1z*inv*g1.z + b1.z; o1.w = d1w*inv*g1.w + b1.w;
    *(float4*)(yr + lane*4) = o0;
    *(float4*)(yr + 128 + lane*4) = o1;
}

// ---------------- per-head attention logit dots ----------------
__global__ __launch_bounds__(256)
void att_logits_kernel(const float* __restrict__ h,
                       const float* __restrict__ att_src,
                       const float* __restrict__ att_dst,
                       float* __restrict__ als, float* __restrict__ ald){
    int row = blockIdx.x;
    int w = threadIdx.x >> 5, lane = threadIdx.x & 31;
    float hv = h[(size_t)row * HID + w * DH + lane];
    float vs = warpSum(hv * att_src[w * DH + lane]);
    float vd = warpSum(hv * att_dst[w * DH + lane]);
    if (lane == 0){
        als[row * HEADS + w] = vs;
        ald[row * HEADS + w] = vd;
    }
}

// ---------------- edge softmax ----------------
__global__ __launch_bounds__(256)
void alpha_kernel(const float* __restrict__ als, const float* __restrict__ ald,
                  float* __restrict__ alpha, int E_tot){
    __shared__ float earr[HEADS][64];
    int b = blockIdx.x / NTOK, n = blockIdx.x % NTOK;
    int head = threadIdx.x >> 5, lane = threadIdx.x & 31;
    int base = g_csr_ptr[n], deg = g_csr_ptr[n+1] - base;
    float aldv = ald[(size_t)(b * NTOK + n) * HEADS + head];
    float m = -1e30f;
    for (int p = lane; p < deg; p += 32){
        int src = g_csr_src[base + p];
        float e = als[(size_t)(b * NTOK + src) * HEADS + head] + aldv;
        e = (e > 0.f) ? e : 0.2f * e;
        earr[head][p] = e;
        m = fmaxf(m, e);
    }
    m = warpMax(m);
    float s = 0.f;
    for (int p = lane; p < deg; p += 32){
        float ex = expf(earr[head][p] - m);
        earr[head][p] = ex;
        s += ex;
    }
    s = warpSum(s);
    float inv = 1.0f / (s + 1e-16f);
    for (int p = lane; p < deg; p += 32)
        alpha[((size_t)b * E_tot + base + p) * HEADS + head] = earr[head][p] * inv;
}

// ---------------- GAT aggregation + bias + residual + fused LN2 ----------------
__global__ __launch_bounds__(256)
void gat_out_ln_kernel(const float* __restrict__ h, const float* __restrict__ alpha,
                       const float* __restrict__ bias, float* __restrict__ x,
                       float* __restrict__ y,
                       const float* __restrict__ g2, const float* __restrict__ b2,
                       int E_tot){
    __shared__ float sm[9];
    int b = blockIdx.x / NTOK, n = blockIdx.x % NTOK;
    int c = threadIdx.x, head = c >> 5;
    int base = g_csr_ptr[n], deg = g_csr_ptr[n+1] - base;
    float acc = 0.f;
    for (int p = 0; p < deg; p++){
        int src = g_csr_src[base + p];
        float a = alpha[((size_t)b * E_tot + base + p) * HEADS + head];
        acc += a * h[(size_t)(b * NTOK + src) * HID + c];
    }
    size_t idx = (size_t)(b * NTOK + n) * HID + c;
    float v = x[idx] + acc + bias[c];
    x[idx] = v;
    // LN2 over the 256 channels (one per thread)
    float mu = blockSum(v, sm) * (1.0f / HID);
    float d = v - mu;
    float var = blockSum(d * d, sm) * (1.0f / HID);
    float inv = rsqrtf(var + 1e-5f);
    y[idx] = d * inv * g2[c] + b2[c];
}

// ---------------- final row softmax ----------------
__global__ __launch_bounds__(256)
void softmax_kernel(const float* __restrict__ logits, float* __restrict__ out){
    __shared__ float sm[9];
    int row = blockIdx.x, t = threadIdx.x;
    float v[4];
    float m = -1e30f;
    #pragma unroll
    for (int k = 0; k < 4; k++){
        int c = t + k * 256;
        v[k] = (c < OUTD) ? logits[(size_t)row * OUTD + c] : -1e30f;
        m = fmaxf(m, v[k]);
    }
    m = blockMax(m, sm);
    float s = 0.f;
    #pragma unroll
    for (int k = 0; k < 4; k++){
        v[k] = expf(v[k] - m);
        int c = t + k * 256;
        if (c < OUTD) s += v[k];
    }
    s = blockSum(s, sm);
    float inv = 1.0f / s;
    #pragma unroll
    for (int k = 0; k < 4; k++){
        int c = t + k * 256;
        if (c < OUTD) out[(size_t)row * OUTD + c] = v[k] * inv;
    }
}

#define TG_SMEM (64*1024)

// ---------------- host launch ----------------
extern "C" void kernel_launch(void* const* d_in, const int* in_sizes, int n_in,
                              void* d_out, int out_size)
{
    const float* images  = (const float*)d_in[0];
    const int*   eidx    = (const int*)  d_in[1];
    const float* Wmap    = (const float*)d_in[2];
    const float* bmap    = (const float*)d_in[3];
    const float* cls_tok = (const float*)d_in[4];
    const float* Wgat    = (const float*)d_in[5];
    const float* att_src = (const float*)d_in[6];
    const float* att_dst = (const float*)d_in[7];
    const float* bgat    = (const float*)d_in[8];
    const float* ln1_g   = (const float*)d_in[9];
    const float* ln1_b   = (const float*)d_in[10];
    const float* ln2_g   = (const float*)d_in[11];
    const float* ln2_b   = (const float*)d_in[12];
    const float* W1      = (const float*)d_in[13];
    const float* b1      = (const float*)d_in[14];
    const float* W2      = (const float*)d_in[15];
    const float* b2      = (const float*)d_in[16];
    const float* Wout    = (const float*)d_in[17];
    const float* bout    = (const float*)d_in[18];

    int E = in_sizes[1] / 2;
    int E_tot = E + NTOK;

    float *x, *y, *h, *mlp, *als, *ald, *alpha, *logits;
    cudaGetSymbolAddress((void**)&x,      g_x);
    cudaGetSymbolAddress((void**)&y,      g_y);
    cudaGetSymbolAddress((void**)&h,      g_h);
    cudaGetSymbolAddress((void**)&mlp,    g_mlp);
    cudaGetSymbolAddress((void**)&als,    g_als);
    cudaGetSymbolAddress((void**)&ald,    g_ald);
    cudaGetSymbolAddress((void**)&alpha,  g_alpha);
    cudaGetSymbolAddress((void**)&logits, g_logits);

    cudaFuncSetAttribute(tgemm<0>, cudaFuncAttributeMaxDynamicSharedMemorySize, TG_SMEM);
    cudaFuncSetAttribute(tgemm<2>, cudaFuncAttributeMaxDynamicSharedMemorySize, TG_SMEM);
    cudaFuncSetAttribute(tgemm<3>, cudaFuncAttributeMaxDynamicSharedMemorySize, TG_SMEM);
    cudaFuncSetAttribute(tgemm<4>, cudaFuncAttributeMaxDynamicSharedMemorySize, TG_SMEM);

    // patch embed: tensor GEMM with image gather + bias + posemb + remap
    tgemm<4><<<dim3(HID/128, PROWS/128), 256, TG_SMEM>>>(images, 0, Wmap, HID, x, HID,
                                                         PROWS, HID, INPUTD, bmap);
    cls_init_kernel<<<BATCH, HID>>>(cls_tok, x);
    build_csr_kernel<<<1, 64>>>(eidx, E);

    for (int l = 0; l < 4; l++){
        ln_kernel<<<ROWS/8, 256>>>(x, y, ln1_g + l*HID, ln1_b + l*HID);
        tgemm<0><<<dim3(HID/128, ROWS/128), 256, TG_SMEM>>>(y, HID, Wgat + (size_t)l*HID*HID, HID,
                                                            h, HID, ROWS, HID, HID, nullptr);
        att_logits_kernel<<<ROWS, 256>>>(h, att_src + l*HID, att_dst + l*HID, als, ald);
        alpha_kernel<<<ROWS, 256>>>(als, ald, alpha, E_tot);
        gat_out_ln_kernel<<<ROWS, 256>>>(h, alpha, bgat + l*HID, x, y,
                                         ln2_g + l*HID, ln2_b + l*HID, E_tot);

        tgemm<2><<<dim3(MLPD/128, ROWS/128), 256, TG_SMEM>>>(y, HID, W1 + (size_t)l*HID*MLPD, MLPD,
                                                             mlp, MLPD, ROWS, MLPD, HID, b1 + l*MLPD);
        tgemm<3><<<dim3(HID/128, ROWS/128), 256, TG_SMEM>>>(mlp, MLPD, W2 + (size_t)l*MLPD*HID, HID,
                                                            x, HID, ROWS, HID, MLPD, b2 + l*HID);
    }

    gemm64<<<dim3((OUTD+63)/64, BATCH/64), 256>>>(x, NTOK*HID, Wout, OUTD,
                                                  logits, OUTD, BATCH, OUTD, HID, bout);
    softmax_kernel<<<BATCH, 256>>>(logits, (float*)d_out);
    (void)n_in; (void)out_size;
}

// round 11
// speedup vs baseline: 1.2181x; 1.1059x over previous
#include <cuda_runtime.h>
#include <cuda_fp16.h>
#include <cuda_bf16.h>
#include <cstdint>
#include <cstddef>

// ---------------- problem constants ----------------
#define BATCH   256
#define NTOK    50
#define NP      7
#define HID     256
#define HEADS   8
#define DH      32
#define MLPD    1024
#define OUTD    1000
#define PS      32
#define IMG     224
#define INPUTD  3072
#define ROWS    (BATCH*NTOK)      // 12800
#define PROWS   (BATCH*NP*NP)     // 12544
#define EMAX    512

// ---------------- device scratch ----------------
__device__ float g_x[ROWS*HID];
__device__ float g_y[ROWS*HID];
__device__ float g_h[ROWS*HID];
__device__ float g_mlp[ROWS*MLPD];
__device__ float g_als[ROWS*HEADS];
__device__ float g_ald[ROWS*HEADS];
__device__ float g_logits[BATCH*OUTD];
__device__ int   g_csr_ptr[NTOK+1];
__device__ int   g_csr_src[1024];

// ---------------- helpers ----------------
__device__ __forceinline__ float warpSum(float v){
    #pragma unroll
    for (int o=16;o;o>>=1) v += __shfl_xor_sync(0xffffffffu, v, o);
    return v;
}
__device__ __forceinline__ float warpMax(float v){
    #pragma unroll
    for (int o=16;o;o>>=1) v = fmaxf(v, __shfl_xor_sync(0xffffffffu, v, o));
    return v;
}
__device__ __forceinline__ float blockSum(float v, float* sm){
    int lane = threadIdx.x & 31, w = threadIdx.x >> 5;
    v = warpSum(v);
    if (lane == 0) sm[w] = v;
    __syncthreads();
    if (threadIdx.x == 0){
        float s = 0.f;
        for (int i = 0; i < 8; i++) s += sm[i];
        sm[8] = s;
    }
    __syncthreads();
    return sm[8];
}
__device__ __forceinline__ float blockMax(float v, float* sm){
    int lane = threadIdx.x & 31, w = threadIdx.x >> 5;
    v = warpMax(v);
    if (lane == 0) sm[w] = v;
    __syncthreads();
    if (threadIdx.x == 0){
        float s = sm[0];
        for (int i = 1; i < 8; i++) s = fmaxf(s, sm[i]);
        sm[8] = s;
    }
    __syncthreads();
    return sm[8];
}
__device__ __forceinline__ float gelu_exact(float v){
    return 0.5f * v * (1.0f + erff(v * 0.7071067811865475f));
}
// pack two fp32 into half2-as-u32 (hi parts) and (lo parts)
__device__ __forceinline__ void hilo_pack(float x, float y, unsigned& uh, unsigned& ul){
    __half hx = __float2half_rn(x);
    __half hy = __float2half_rn(y);
    __half lx = __float2half_rn(x - __half2float(hx));
    __half ly = __float2half_rn(y - __half2float(hy));
    __half2 th = __halves2half2(hx, hy);
    __half2 tl = __halves2half2(lx, ly);
    uh = *reinterpret_cast<unsigned*>(&th);
    ul = *reinterpret_cast<unsigned*>(&tl);
}
__device__ __forceinline__ void mma_f16(float* d, const unsigned* a, const unsigned* b){
    asm volatile(
        "mma.sync.aligned.m16n8k16.row.col.f32.f16.f16.f32 "
        "{%0,%1,%2,%3}, {%4,%5,%6,%7}, {%8,%9}, {%0,%1,%2,%3};\n"
        : "+f"(d[0]), "+f"(d[1]), "+f"(d[2]), "+f"(d[3])
        : "r"(a[0]), "r"(a[1]), "r"(a[2]), "r"(a[3]), "r"(b[0]), "r"(b[1]));
}

// =============================================================
// 3xFP16 tensor-core GEMM: 128x128x32 CTA tile, 8 warps (64x32 each)
// Double-buffered smem stages; __launch_bounds__(256,2) forces <=128 regs
// so 2 CTAs/SM can co-reside (latency hiding across CTAs).
// MODE 0: C = A@B
// MODE 2: C = gelu(A@B + bias)
// MODE 3: C = C + A@B + bias
// MODE 4: patch-embed (A gathered from images, +bias+posemb, row remap)
// =============================================================
template<int MODE>
__global__ __launch_bounds__(256, 2)
void tgemm(const float* __restrict__ A, int lda,
           const float* __restrict__ B, int ldb,
           float* __restrict__ C, int ldc,
           int M, int N, int K,
           const float* __restrict__ bias)
{
    // per stage (8192 u32): sAh[2048] sAl[2048] sBh[2048] sBl[2048]
    extern __shared__ unsigned dsm[];

    const int tx   = threadIdx.x;
    const int wid  = tx >> 5;
    const int lane = tx & 31;
    const int warp_m = wid >> 2;     // 0..1
    const int warp_n = wid & 3;      // 0..3
    const int bm = blockIdx.y * 128;
    const int bn = blockIdx.x * 128;

    const int a_m  = tx >> 3;        // 0..31
    const int a_kv = tx & 7;         // k quad
    const int b_q  = tx & 31;        // n quad

    float acc[4][4][4] = {};

    float4 ar[4];
    float4 br0[2], br1[2];

    auto load_stage = [&](int k0){
        #pragma unroll
        for (int it = 0; it < 4; it++){
            int m = a_m + 32*it;
            if (MODE == 4){
                int mg = bm + m;
                int gb = mg / (NP*NP);
                int p  = mg % (NP*NP);
                int gi = p / NP, gj = p % NP;
                int k  = k0 + a_kv*4;
                int c  = k >> 10;
                int rem = k & 1023;
                int hh = rem >> 5, ww = rem & 31;
                size_t off = ((size_t)(gb*3 + c) * IMG + (gi*PS + hh)) * IMG + gj*PS + ww;
                ar[it] = *(const float4*)(A + off);
            } else {
                ar[it] = *(const float4*)(A + (size_t)(bm + m) * lda + k0 + a_kv*4);
            }
        }
        #pragma unroll
        for (int it = 0; it < 2; it++){
            int krow = (wid << 1) + (it << 4);
            br0[it] = *(const float4*)(B + (size_t)(k0 + krow    ) * ldb + bn + b_q*4);
            br1[it] = *(const float4*)(B + (size_t)(k0 + krow + 1) * ldb + bn + b_q*4);
        }
    };

    auto store_stage = [&](int buf){
        unsigned* sAh = dsm + buf*8192;
        unsigned* sAl = sAh + 2048;
        unsigned* sBh = sAh + 4096;
        unsigned* sBl = sAh + 6144;
        #pragma unroll
        for (int it = 0; it < 4; it++){
            int m   = a_m + 32*it;
            int ks  = a_kv >> 2;
            int c   = (a_kv & 3) << 2;
            int kp0 = c >> 1;
            int g   = (m >> 4)*2 + ks;
            int reg = ((m & 15) >> 3) + ((kp0 & 4) ? 2 : 0);
            int lane0 = (m & 7)*4 + (kp0 & 3);
            int base = g*128 + reg*32;
            unsigned uh, ul;
            hilo_pack(ar[it].x, ar[it].y, uh, ul);
            sAh[base + lane0]     = uh;  sAl[base + lane0]     = ul;
            hilo_pack(ar[it].z, ar[it].w, uh, ul);
            sAh[base + lane0 + 1] = uh;  sAl[base + lane0 + 1] = ul;
        }
        #pragma unroll
        for (int it = 0; it < 2; it++){
            int reg = (wid >> 2) & 1;
            int w3  = wid & 3;
            const float* r0 = (const float*)&br0[it];
            const float* r1 = (const float*)&br1[it];
            #pragma unroll
            for (int j = 0; j < 4; j++){
                int n  = b_q*4 + j;
                int g  = (n >> 3)*2 + it;
                int s  = (n >> 3) & 7;
                int ln = (((n & 7)*4 + w3) ^ s);
                unsigned uh, ul;
                hilo_pack(r0[j], r1[j], uh, ul);
                sBh[g*64 + reg*32 + ln] = uh;
                sBl[g*64 + reg*32 + ln] = ul;
            }
        }
    };

    auto compute = [&](int buf){
        unsigned* sAh = dsm + buf*8192;
        unsigned* sAl = sAh + 2048;
        unsigned* sBh = sAh + 4096;
        unsigned* sBl = sAh + 6144;
        #pragma unroll
        for (int ks = 0; ks < 2; ks++){
            unsigned ah[4][4], al[4][4];
            unsigned bh[4][2], bl[4][2];
            #pragma unroll
            for (int mt = 0; mt < 4; mt++){
                int g = (warp_m*4 + mt)*2 + ks;
                int base = g*128;
                #pragma unroll
                for (int r = 0; r < 4; r++){
                    ah[mt][r] = sAh[base + r*32 + lane];
                    al[mt][r] = sAl[base + r*32 + lane];
                }
            }
            #pragma unroll
            for (int nt = 0; nt < 4; nt++){
                int ntile = warp_n*4 + nt;
                int g  = ntile*2 + ks;
                int ln = lane ^ (ntile & 7);
                bh[nt][0] = sBh[g*64 + ln];   bh[nt][1] = sBh[g*64 + 32 + ln];
                bl[nt][0] = sBl[g*64 + ln];   bl[nt][1] = sBl[g*64 + 32 + ln];
            }
            #pragma unroll
            for (int mt = 0; mt < 4; mt++)
                #pragma unroll
                for (int nt = 0; nt < 4; nt++){
                    mma_f16(acc[mt][nt], al[mt], bh[nt]);
                    mma_f16(acc[mt][nt], ah[mt], bl[nt]);
                    mma_f16(acc[mt][nt], ah[mt], bh[nt]);
                }
        }
    };

    load_stage(0);
    store_stage(0);
    __syncthreads();

    const int NS = K / 32;
    for (int kt = 0; kt < NS; kt++){
        if (kt + 1 < NS) load_stage((kt + 1) * 32);
        compute(kt & 1);
        if (kt + 1 < NS){
            store_stage((kt + 1) & 1);
            __syncthreads();
        }
    }

    // ---- epilogue ----
    #pragma unroll
    for (int mt = 0; mt < 4; mt++){
        int r0 = bm + warp_m*64 + mt*16 + (lane >> 2);
        #pragma unroll
        for (int half = 0; half < 2; half++){
            int row = r0 + half*8;
            int orow = row;
            int tpos = 0;
            if (MODE == 4){
                int b = row / (NP*NP);
                int p = row % (NP*NP);
                tpos = p + 1;
                orow = b * NTOK + tpos;
            }
            #pragma unroll
            for (int nt = 0; nt < 4; nt++){
                int c0 = bn + warp_n*32 + nt*8 + ((lane & 3) << 1);
                float v0 = acc[mt][nt][half*2 + 0];
                float v1 = acc[mt][nt][half*2 + 1];
                if (MODE >= 2){ v0 += bias[c0]; v1 += bias[c0+1]; }
                if (MODE == 2){ v0 = gelu_exact(v0); v1 = gelu_exact(v1); }
                if (MODE == 4){
                    float fac = expf(-(float)c0 * 0.03597789207803285f);
                    float ang = (float)tpos * fac;
                    float s, c;
                    sincosf(ang, &s, &c);
                    v0 += s; v1 += c;
                }
                float* cp = C + (size_t)orow * ldc + c0;
                if (MODE == 3){
                    float2 old = *(const float2*)cp;
                    v0 += old.x; v1 += old.y;
                }
                float2 o; o.x = v0; o.y = v1;
                *(float2*)cp = o;
            }
        }
    }
}

// ---------------- SIMT GEMM (small head GEMM: +bias) ----------------
__global__ __launch_bounds__(256)
void gemm64(const float* __restrict__ A, int lda,
            const float* __restrict__ B, int ldb,
            float* __restrict__ C, int ldc,
            int M, int N, int K,
            const float* __restrict__ bias)
{
    __shared__ float As[16][64];
    __shared__ float Bs[16][68];

    const int tx = threadIdx.x;
    const int bm = blockIdx.y * 64;
    const int bn = blockIdx.x * 64;

    const int am  = tx >> 2;
    const int ak  = (tx & 3) << 2;
    const int bk  = tx >> 4;
    const int bnn = (tx & 15) << 2;
    const int tm  = (tx >> 4) << 2;
    const int tn  = (tx & 15) << 2;

    const int arow = bm + am;

    float acc[4][4];
    #pragma unroll
    for (int i=0;i<4;i++)
        #pragma unroll
        for (int j=0;j<4;j++) acc[i][j] = 0.f;

    for (int k0 = 0; k0 < K; k0 += 16){
        float4 av = make_float4(0.f,0.f,0.f,0.f);
        if (arow < M)
            av = *(const float4*)(A + (size_t)arow * lda + k0 + ak);
        As[ak+0][am] = av.x; As[ak+1][am] = av.y;
        As[ak+2][am] = av.z; As[ak+3][am] = av.w;

        float4 bv = make_float4(0.f,0.f,0.f,0.f);
        if (bn + bnn < N)
            bv = *(const float4*)(B + (size_t)(k0 + bk) * ldb + bn + bnn);
        *(float4*)&Bs[bk][bnn] = bv;

        __syncthreads();
        #pragma unroll
        for (int kk = 0; kk < 16; kk++){
            float4 a = *(const float4*)&As[kk][tm];
            float4 b = *(const float4*)&Bs[kk][tn];
            acc[0][0] += a.x*b.x; acc[0][1] += a.x*b.y; acc[0][2] += a.x*b.z; acc[0][3] += a.x*b.w;
            acc[1][0] += a.y*b.x; acc[1][1] += a.y*b.y; acc[1][2] += a.y*b.z; acc[1][3] += a.y*b.w;
            acc[2][0] += a.z*b.x; acc[2][1] += a.z*b.y; acc[2][2] += a.z*b.z; acc[2][3] += a.z*b.w;
            acc[3][0] += a.w*b.x; acc[3][1] += a.w*b.y; acc[3][2] += a.w*b.z; acc[3][3] += a.w*b.w;
        }
        __syncthreads();
    }

    #pragma unroll
    for (int i=0;i<4;i++){
        int row = bm + tm + i;
        if (row >= M) continue;
        #pragma unroll
        for (int j=0;j<4;j++){
            int col = bn + tn + j;
            if (col >= N) continue;
            C[(size_t)row * ldc + col] = acc[i][j] + bias[col];
        }
    }
}

// ---------------- CLS token init ----------------
__global__ void cls_init_kernel(const float* __restrict__ cls, float* __restrict__ x){
    int b = blockIdx.x, c = threadIdx.x;
    x[(size_t)b * NTOK * HID + c] = cls[c] + ((c & 1) ? 1.0f : 0.0f);
}

// ---------------- CSR build ----------------
__global__ void build_csr_kernel(const int* __restrict__ edge_index, int E){
    __shared__ int s_src[EMAX], s_dst[EMAX], cnt[NTOK];
    int t = threadIdx.x;
    for (int e = t; e < E; e += 64){
        s_src[e] = edge_index[e];
        s_dst[e] = edge_index[E + e];
    }
    __syncthreads();
    if (t < NTOK){
        int c = 1;
        for (int e = 0; e < E; e++) if (s_dst[e] == t) c++;
        cnt[t] = c;
    }
    __syncthreads();
    if (t == 0){
        int s = 0;
        for (int n = 0; n < NTOK; n++){ g_csr_ptr[n] = s; s += cnt[n]; }
        g_csr_ptr[NTOK] = s;
    }
    __syncthreads();
    if (t < NTOK){
        int pos = g_csr_ptr[t];
        for (int e = 0; e < E; e++) if (s_dst[e] == t) g_csr_src[pos++] = s_src[e];
        g_csr_src[pos++] = t;
    }
}

// ---------------- LayerNorm (warp-per-row, float out) ----------------
__global__ __launch_bounds__(256)
void ln_kernel(const float* __restrict__ x, float* __restrict__ y,
               const float* __restrict__ g, const float* __restrict__ b){
    int row  = blockIdx.x * 8 + (threadIdx.x >> 5);
    int lane = threadIdx.x & 31;
    const float* xr = x + (size_t)row * HID;
    float4 v0 = *(const float4*)(xr + lane*4);
    float4 v1 = *(const float4*)(xr + 128 + lane*4);
    float s = v0.x+v0.y+v0.z+v0.w + v1.x+v1.y+v1.z+v1.w;
    float mu = warpSum(s) * (1.0f / HID);
    float d0x=v0.x-mu, d0y=v0.y-mu, d0z=v0.z-mu, d0w=v0.w-mu;
    float d1x=v1.x-mu, d1y=v1.y-mu, d1z=v1.z-mu, d1w=v1.w-mu;
    float q = d0x*d0x+d0y*d0y+d0z*d0z+d0w*d0w + d1x*d1x+d1y*d1y+d1z*d1z+d1w*d1w;
    float var = warpSum(q) * (1.0f / HID);
    float inv = rsqrtf(var + 1e-5f);
    float4 g0 = *(const float4*)(g + lane*4);
    float4 g1 = *(const float4*)(g + 128 + lane*4);
    float4 b0 = *(const float4*)(b + lane*4);
    float4 b1 = *(const float4*)(b + 128 + lane*4);
    float* yr = y + (size_t)row * HID;
    float4 o0, o1;
    o0.x = d0x*inv*g0.x + b0.x; o0.y = d0y*inv*g0.y + b0.y;
    o0.z = d0z*inv*g0.z + b0.z; o0.w = d0w*inv*g0.w + b0.w;
    o1.x = d1x*inv*g1.x + b1.x; o1.y = d1y*inv*g1.y + b1.y;
    o1.z = d1z*inv*g1.z + b1.z; o1.w = d1w*inv*g1.w + b1.w;
    *(float4*)(yr + lane*4) = o0;
    *(float4*)(yr + 128 + lane*4) = o1;
}

// ---------------- per-head attention logit dots ----------------
__global__ __launch_bounds__(256)
void att_logits_kernel(const float* __restrict__ h,
                       const float* __restrict__ att_src,
                       const float* __restrict__ att_dst,
                       float* __restrict__ als, float* __restrict__ ald){
    int row = blockIdx.x;
    int w = threadIdx.x >> 5, lane = threadIdx.x & 31;
    float hv = h[(size_t)row * HID + w * DH + lane];
    float vs = warpSum(hv * att_src[w * DH + lane]);
    float vd = warpSum(hv * att_dst[w * DH + lane]);
    if (lane == 0){
        als[row * HEADS + w] = vs;
        ald[row * HEADS + w] = vd;
    }
}

// ---- fused: edge softmax + GAT aggregation + bias + residual + LN2 ----
// NOTE: deg can be up to 50 (CLS node) -> strided loops over p, NOT lane-only.
__global__ __launch_bounds__(256)
void gat_fused_kernel(const float* __restrict__ h,
                      const float* __restrict__ als, const float* __restrict__ ald,
                      const float* __restrict__ bias, float* __restrict__ x,
                      float* __restrict__ y,
                      const float* __restrict__ g2, const float* __restrict__ b2){
    __shared__ float alpha_s[HEADS][64];
    __shared__ float sm[9];
    int b = blockIdx.x / NTOK, n = blockIdx.x % NTOK;
    int c = threadIdx.x;
    int head = c >> 5, lane = c & 31;
    int base = g_csr_ptr[n], deg = g_csr_ptr[n+1] - base;

    // per-head softmax over incoming edges (warp per head; deg <= 64)
    {
        float aldv = ald[(size_t)(b * NTOK + n) * HEADS + head];
        float m = -1e30f;
        for (int p = lane; p < deg; p += 32){
            int src = g_csr_src[base + p];
            float e = als[(size_t)(b * NTOK + src) * HEADS + head] + aldv;
            e = (e > 0.f) ? e : 0.2f * e;   // LeakyReLU(0.2)
            alpha_s[head][p] = e;
            m = fmaxf(m, e);
        }
        m = warpMax(m);
        float s = 0.f;
        for (int p = lane; p < deg; p += 32){
            float ex = expf(alpha_s[head][p] - m);
            alpha_s[head][p] = ex;
            s += ex;
        }
        s = warpSum(s);
        float inv = 1.0f / (s + 1e-16f);
        for (int p = lane; p < deg; p += 32)
            alpha_s[head][p] *= inv;
    }
    __syncthreads();

    // aggregation: thread c owns channel c (head = c>>5)
    float acc = 0.f;
    for (int p = 0; p < deg; p++){
        int src = g_csr_src[base + p];
        acc += alpha_s[head][p] * h[(size_t)(b * NTOK + src) * HID + c];
    }
    size_t idx = (size_t)(b * NTOK + n) * HID + c;
    float v = x[idx] + acc + bias[c];
    x[idx] = v;

    // fused LN2
    float mu = blockSum(v, sm) * (1.0f / HID);
    float d = v - mu;
    float var = blockSum(d * d, sm) * (1.0f / HID);
    float inv = rsqrtf(var + 1e-5f);
    y[idx] = d * inv * g2[c] + b2[c];
}

// ---------------- final row softmax ----------------
__global__ __launch_bounds__(256)
void softmax_kernel(const float* __restrict__ logits, float* __restrict__ out){
    __shared__ float sm[9];
    int row = blockIdx.x, t = threadIdx.x;
    float v[4];
    float m = -1e30f;
    #pragma unroll
    for (int k = 0; k < 4; k++){
        int c = t + k * 256;
        v[k] = (c < OUTD) ? logits[(size_t)row * OUTD + c] : -1e30f;
        m = fmaxf(m, v[k]);
    }
    m = blockMax(m, sm);
    float s = 0.f;
    #pragma unroll
    for (int k = 0; k < 4; k++){
        v[k] = expf(v[k] - m);
        int c = t + k * 256;
        if (c < OUTD) s += v[k];
    }
    s = blockSum(s, sm);
    float inv = 1.0f / s;
    #pragma unroll
    for (int k = 0; k < 4; k++){
        int c = t + k * 256;
        if (c < OUTD) out[(size_t)row * OUTD + c] = v[k] * inv;
    }
}

#define TG_SMEM (64*1024)

// ---------------- host launch ----------------
extern "C" void kernel_launch(void* const* d_in, const int* in_sizes, int n_in,
                              void* d_out, int out_size)
{
    const float* images  = (const float*)d_in[0];
    const int*   eidx    = (const int*)  d_in[1];
    const float* Wmap    = (const float*)d_in[2];
    const float* bmap    = (const float*)d_in[3];
    const float* cls_tok = (const float*)d_in[4];
    const float* Wgat    = (const float*)d_in[5];
    const float* att_src = (const float*)d_in[6];
    const float* att_dst = (const float*)d_in[7];
    const float* bgat    = (const float*)d_in[8];
    const float* ln1_g   = (const float*)d_in[9];
    const float* ln1_b   = (const float*)d_in[10];
    const float* ln2_g   = (const float*)d_in[11];
    const float* ln2_b   = (const float*)d_in[12];
    const float* W1      = (const float*)d_in[13];
    const float* b1      = (const float*)d_in[14];
    const float* W2      = (const float*)d_in[15];
    const float* b2      = (const float*)d_in[16];
    const float* Wout    = (const float*)d_in[17];
    const float* bout    = (const float*)d_in[18];

    int E = in_sizes[1] / 2;

    float *x, *y, *h, *mlp, *als, *ald, *logits;
    cudaGetSymbolAddress((void**)&x,      g_x);
    cudaGetSymbolAddress((void**)&y,      g_y);
    cudaGetSymbolAddress((void**)&h,      g_h);
    cudaGetSymbolAddress((void**)&mlp,    g_mlp);
    cudaGetSymbolAddress((void**)&als,    g_als);
    cudaGetSymbolAddress((void**)&ald,    g_ald);
    cudaGetSymbolAddress((void**)&logits, g_logits);

    cudaFuncSetAttribute(tgemm<0>, cudaFuncAttributeMaxDynamicSharedMemorySize, TG_SMEM);
    cudaFuncSetAttribute(tgemm<2>, cudaFuncAttributeMaxDynamicSharedMemorySize, TG_SMEM);
    cudaFuncSetAttribute(tgemm<3>, cudaFuncAttributeMaxDynamicSharedMemorySize, TG_SMEM);
    cudaFuncSetAttribute(tgemm<4>, cudaFuncAttributeMaxDynamicSharedMemorySize, TG_SMEM);

    // patch embed: tensor GEMM with image gather + bias + posemb + remap
    tgemm<4><<<dim3(HID/128, PROWS/128), 256, TG_SMEM>>>(images, 0, Wmap, HID, x, HID,
                                                         PROWS, HID, INPUTD, bmap);
    cls_init_kernel<<<BATCH, HID>>>(cls_tok, x);
    build_csr_kernel<<<1, 64>>>(eidx, E);

    for (int l = 0; l < 4; l++){
        ln_kernel<<<ROWS/8, 256>>>(x, y, ln1_g + l*HID, ln1_b + l*HID);
        tgemm<0><<<dim3(HID/128, ROWS/128), 256, TG_SMEM>>>(y, HID, Wgat + (size_t)l*HID*HID, HID,
                                                            h, HID, ROWS, HID, HID, nullptr);
        att_logits_kernel<<<ROWS, 256>>>(h, att_src + l*HID, att_dst + l*HID, als, ald);
        gat_fused_kernel<<<ROWS, 256>>>(h, als, ald, bgat + l*HID, x, y,
                                        ln2_g + l*HID, ln2_b + l*HID);

        tgemm<2><<<dim3(MLPD/128, ROWS/128), 256, TG_SMEM>>>(y, HID, W1 + (size_t)l*HID*MLPD, MLPD,
                                                             mlp, MLPD, ROWS, MLPD, HID, b1 + l*MLPD);
        tgemm<3><<<dim3(HID/128, ROWS/128), 256, TG_SMEM>>>(mlp, MLPD, W2 + (size_t)l*MLPD*HID, HID,
                                                            x, HID, ROWS, HID, MLPD, b2 + l*HID);
    }

    gemm64<<<dim3((OUTD+63)/64, BATCH/64), 256>>>(x, NTOK*HID, Wout, OUTD,
                                                  logits, OUTD, BATCH, OUTD, HID, bout);
    softmax_kernel<<<BATCH, 256>>>(logits, (float*)d_out);
    (void)n_in; (void)out_size;
}

// round 12
// speedup vs baseline: 1.5152x; 1.2439x over previous
#include <cuda_runtime.h>
#include <cuda_fp16.h>
#include <cuda_bf16.h>
#include <cstdint>
#include <cstddef>

// ---------------- problem constants ----------------
#define BATCH   256
#define NTOK    50
#define NP      7
#define HID     256
#define HEADS   8
#define DH      32
#define MLPD    1024
#define OUTD    1000
#define PS      32
#define IMG     224
#define INPUTD  3072
#define ROWS    (BATCH*NTOK)      // 12800
#define PROWS   (BATCH*NP*NP)     // 12544
#define EMAX    512

// ---------------- device scratch ----------------
__device__ float g_x[ROWS*HID];
__device__ float g_y[ROWS*HID];
__device__ float g_h[ROWS*HID];
__device__ float g_mlp[ROWS*MLPD];
__device__ float g_als[ROWS*HEADS];
__device__ float g_ald[ROWS*HEADS];
__device__ float g_logits[BATCH*OUTD];
__device__ int   g_csr_ptr[NTOK+1];
__device__ int   g_csr_src[1024];

// ---------------- helpers ----------------
__device__ __forceinline__ float warpSum(float v){
    #pragma unroll
    for (int o=16;o;o>>=1) v += __shfl_xor_sync(0xffffffffu, v, o);
    return v;
}
__device__ __forceinline__ float warpMax(float v){
    #pragma unroll
    for (int o=16;o;o>>=1) v = fmaxf(v, __shfl_xor_sync(0xffffffffu, v, o));
    return v;
}
__device__ __forceinline__ float blockSum(float v, float* sm){
    int lane = threadIdx.x & 31, w = threadIdx.x >> 5;
    v = warpSum(v);
    if (lane == 0) sm[w] = v;
    __syncthreads();
    if (threadIdx.x == 0){
        float s = 0.f;
        for (int i = 0; i < 8; i++) s += sm[i];
        sm[8] = s;
    }
    __syncthreads();
    return sm[8];
}
__device__ __forceinline__ float blockMax(float v, float* sm){
    int lane = threadIdx.x & 31, w = threadIdx.x >> 5;
    v = warpMax(v);
    if (lane == 0) sm[w] = v;
    __syncthreads();
    if (threadIdx.x == 0){
        float s = sm[0];
        for (int i = 1; i < 8; i++) s = fmaxf(s, sm[i]);
        sm[8] = s;
    }
    __syncthreads();
    return sm[8];
}
__device__ __forceinline__ float gelu_exact(float v){
    return 0.5f * v * (1.0f + erff(v * 0.7071067811865475f));
}
// split-pack: hi/lo halves of (x,y) as half2-u32
__device__ __forceinline__ void hilo_pack(float x, float y, unsigned& uh, unsigned& ul){
    __half hx = __float2half_rn(x);
    __half hy = __float2half_rn(y);
    __half lx = __float2half_rn(x - __half2float(hx));
    __half ly = __float2half_rn(y - __half2float(hy));
    __half2 th = __halves2half2(hx, hy);
    __half2 tl = __halves2half2(lx, ly);
    uh = *reinterpret_cast<unsigned*>(&th);
    ul = *reinterpret_cast<unsigned*>(&tl);
}
// plain pack: hi halves only
__device__ __forceinline__ unsigned h_pack(float x, float y){
    __half2 t = __halves2half2(__float2half_rn(x), __float2half_rn(y));
    return *reinterpret_cast<unsigned*>(&t);
}
__device__ __forceinline__ void mma_f16(float* d, const unsigned* a, const unsigned* b){
    asm volatile(
        "mma.sync.aligned.m16n8k16.row.col.f32.f16.f16.f32 "
        "{%0,%1,%2,%3}, {%4,%5,%6,%7}, {%8,%9}, {%0,%1,%2,%3};\n"
        : "+f"(d[0]), "+f"(d[1]), "+f"(d[2]), "+f"(d[3])
        : "r"(a[0]), "r"(a[1]), "r"(a[2]), "r"(a[3]), "r"(b[0]), "r"(b[1]));
}

// =============================================================
// 2xFP16 tensor-core GEMM (A exactly split hi/lo, B hi only):
// D = (Ah + Al) @ Bh  -> error = A (B - Bh) ~ 2^-11 relative.
// 128x128x32 CTA tile, 8 warps (64x32 each), double-buffered smem,
// __launch_bounds__(256,2) for 2 CTAs/SM.
// MODE 0: C = A@B ; MODE 2: gelu(A@B+bias) ; MODE 3: C += A@B + bias
// MODE 4: patch-embed (image gather, +bias+posemb, row remap)
// =============================================================
template<int MODE>
__global__ __launch_bounds__(256, 2)
void tgemm(const float* __restrict__ A, int lda,
           const float* __restrict__ B, int ldb,
           float* __restrict__ C, int ldc,
           int M, int N, int K,
           const float* __restrict__ bias)
{
    // per stage (6144 u32): sAh[2048] sAl[2048] sBh[2048]
    extern __shared__ unsigned dsm[];

    const int tx   = threadIdx.x;
    const int wid  = tx >> 5;
    const int lane = tx & 31;
    const int warp_m = wid >> 2;     // 0..1
    const int warp_n = wid & 3;      // 0..3
    const int bm = blockIdx.y * 128;
    const int bn = blockIdx.x * 128;

    const int a_m  = tx >> 3;        // 0..31
    const int a_kv = tx & 7;         // k quad
    const int b_q  = tx & 31;        // n quad

    float acc[4][4][4] = {};

    float4 ar[4];
    float4 br0[2], br1[2];

    auto load_stage = [&](int k0){
        #pragma unroll
        for (int it = 0; it < 4; it++){
            int m = a_m + 32*it;
            if (MODE == 4){
                int mg = bm + m;
                int gb = mg / (NP*NP);
                int p  = mg % (NP*NP);
                int gi = p / NP, gj = p % NP;
                int k  = k0 + a_kv*4;
                int c  = k >> 10;
                int rem = k & 1023;
                int hh = rem >> 5, ww = rem & 31;
                size_t off = ((size_t)(gb*3 + c) * IMG + (gi*PS + hh)) * IMG + gj*PS + ww;
                ar[it] = *(const float4*)(A + off);
            } else {
                ar[it] = *(const float4*)(A + (size_t)(bm + m) * lda + k0 + a_kv*4);
            }
        }
        #pragma unroll
        for (int it = 0; it < 2; it++){
            int krow = (wid << 1) + (it << 4);
            br0[it] = *(const float4*)(B + (size_t)(k0 + krow    ) * ldb + bn + b_q*4);
            br1[it] = *(const float4*)(B + (size_t)(k0 + krow + 1) * ldb + bn + b_q*4);
        }
    };

    auto store_stage = [&](int buf){
        unsigned* sAh = dsm + buf*6144;
        unsigned* sAl = sAh + 2048;
        unsigned* sBh = sAh + 4096;
        #pragma unroll
        for (int it = 0; it < 4; it++){
            int m   = a_m + 32*it;
            int ks  = a_kv >> 2;
            int c   = (a_kv & 3) << 2;
            int kp0 = c >> 1;
            int g   = (m >> 4)*2 + ks;
            int reg = ((m & 15) >> 3) + ((kp0 & 4) ? 2 : 0);
            int lane0 = (m & 7)*4 + (kp0 & 3);
            int base = g*128 + reg*32;
            unsigned uh, ul;
            hilo_pack(ar[it].x, ar[it].y, uh, ul);
            sAh[base + lane0]     = uh;  sAl[base + lane0]     = ul;
            hilo_pack(ar[it].z, ar[it].w, uh, ul);
            sAh[base + lane0 + 1] = uh;  sAl[base + lane0 + 1] = ul;
        }
        #pragma unroll
        for (int it = 0; it < 2; it++){
            int reg = (wid >> 2) & 1;
            int w3  = wid & 3;
            const float* r0 = (const float*)&br0[it];
            const float* r1 = (const float*)&br1[it];
            #pragma unroll
            for (int j = 0; j < 4; j++){
                int n  = b_q*4 + j;
                int g  = (n >> 3)*2 + it;
                int s  = (n >> 3) & 7;
                int ln = (((n & 7)*4 + w3) ^ s);
                sBh[g*64 + reg*32 + ln] = h_pack(r0[j], r1[j]);
            }
        }
    };

    auto compute = [&](int buf){
        unsigned* sAh = dsm + buf*6144;
        unsigned* sAl = sAh + 2048;
        unsigned* sBh = sAh + 4096;
        #pragma unroll
        for (int ks = 0; ks < 2; ks++){
            unsigned ah[4][4], al[4][4];
            unsigned bh[4][2];
            #pragma unroll
            for (int mt = 0; mt < 4; mt++){
                int g = (warp_m*4 + mt)*2 + ks;
                int base = g*128;
                #pragma unroll
                for (int r = 0; r < 4; r++){
                    ah[mt][r] = sAh[base + r*32 + lane];
                    al[mt][r] = sAl[base + r*32 + lane];
                }
            }
            #pragma unroll
            for (int nt = 0; nt < 4; nt++){
                int ntile = warp_n*4 + nt;
                int g  = ntile*2 + ks;
                int ln = lane ^ (ntile & 7);
                bh[nt][0] = sBh[g*64 + ln];   bh[nt][1] = sBh[g*64 + 32 + ln];
            }
            #pragma unroll
            for (int mt = 0; mt < 4; mt++)
                #pragma unroll
                for (int nt = 0; nt < 4; nt++){
                    mma_f16(acc[mt][nt], al[mt], bh[nt]);
                    mma_f16(acc[mt][nt], ah[mt], bh[nt]);
                }
        }
    };

    load_stage(0);
    store_stage(0);
    __syncthreads();

    const int NS = K / 32;
    for (int kt = 0; kt < NS; kt++){
        if (kt + 1 < NS) load_stage((kt + 1) * 32);
        compute(kt & 1);
        if (kt + 1 < NS){
            store_stage((kt + 1) & 1);
            __syncthreads();
        }
    }

    // ---- epilogue ----
    #pragma unroll
    for (int mt = 0; mt < 4; mt++){
        int r0 = bm + warp_m*64 + mt*16 + (lane >> 2);
        #pragma unroll
        for (int half = 0; half < 2; half++){
            int row = r0 + half*8;
            int orow = row;
            int tpos = 0;
            if (MODE == 4){
                int b = row / (NP*NP);
                int p = row % (NP*NP);
                tpos = p + 1;
                orow = b * NTOK + tpos;
            }
            #pragma unroll
            for (int nt = 0; nt < 4; nt++){
                int c0 = bn + warp_n*32 + nt*8 + ((lane & 3) << 1);
                float v0 = acc[mt][nt][half*2 + 0];
                float v1 = acc[mt][nt][half*2 + 1];
                if (MODE >= 2){ v0 += bias[c0]; v1 += bias[c0+1]; }
                if (MODE == 2){ v0 = gelu_exact(v0); v1 = gelu_exact(v1); }
                if (MODE == 4){
                    float fac = expf(-(float)c0 * 0.03597789207803285f);
                    float ang = (float)tpos * fac;
                    float s, c;
                    sincosf(ang, &s, &c);
                    v0 += s; v1 += c;
                }
                float* cp = C + (size_t)orow * ldc + c0;
                if (MODE == 3){
                    float2 old = *(const float2*)cp;
                    v0 += old.x; v1 += old.y;
                }
                float2 o; o.x = v0; o.y = v1;
                *(float2*)cp = o;
            }
        }
    }
}

// ---------------- SIMT GEMM (small head GEMM: +bias) ----------------
__global__ __launch_bounds__(256)
void gemm64(const float* __restrict__ A, int lda,
            const float* __restrict__ B, int ldb,
            float* __restrict__ C, int ldc,
            int M, int N, int K,
            const float* __restrict__ bias)
{
    __shared__ float As[16][64];
    __shared__ float Bs[16][68];

    const int tx = threadIdx.x;
    const int bm = blockIdx.y * 64;
    const int bn = blockIdx.x * 64;

    const int am  = tx >> 2;
    const int ak  = (tx & 3) << 2;
    const int bk  = tx >> 4;
    const int bnn = (tx & 15) << 2;
    const int tm  = (tx >> 4) << 2;
    const int tn  = (tx & 15) << 2;

    const int arow = bm + am;

    float acc[4][4];
    #pragma unroll
    for (int i=0;i<4;i++)
        #pragma unroll
        for (int j=0;j<4;j++) acc[i][j] = 0.f;

    for (int k0 = 0; k0 < K; k0 += 16){
        float4 av = make_float4(0.f,0.f,0.f,0.f);
        if (arow < M)
            av = *(const float4*)(A + (size_t)arow * lda + k0 + ak);
        As[ak+0][am] = av.x; As[ak+1][am] = av.y;
        As[ak+2][am] = av.z; As[ak+3][am] = av.w;

        float4 bv = make_float4(0.f,0.f,0.f,0.f);
        if (bn + bnn < N)
            bv = *(const float4*)(B + (size_t)(k0 + bk) * ldb + bn + bnn);
        *(float4*)&Bs[bk][bnn] = bv;

        __syncthreads();
        #pragma unroll
        for (int kk = 0; kk < 16; kk++){
            float4 a = *(const float4*)&As[kk][tm];
            float4 b = *(const float4*)&Bs[kk][tn];
            acc[0][0] += a.x*b.x; acc[0][1] += a.x*b.y; acc[0][2] += a.x*b.z; acc[0][3] += a.x*b.w;
            acc[1][0] += a.y*b.x; acc[1][1] += a.y*b.y; acc[1][2] += a.y*b.z; acc[1][3] += a.y*b.w;
            acc[2][0] += a.z*b.x; acc[2][1] += a.z*b.y; acc[2][2] += a.z*b.z; acc[2][3] += a.z*b.w;
            acc[3][0] += a.w*b.x; acc[3][1] += a.w*b.y; acc[3][2] += a.w*b.z; acc[3][3] += a.w*b.w;
        }
        __syncthreads();
    }

    #pragma unroll
    for (int i=0;i<4;i++){
        int row = bm + tm + i;
        if (row >= M) continue;
        #pragma unroll
        for (int j=0;j<4;j++){
            int col = bn + tn + j;
            if (col >= N) continue;
            C[(size_t)row * ldc + col] = acc[i][j] + bias[col];
        }
    }
}

// ---------------- CLS token init ----------------
__global__ void cls_init_kernel(const float* __restrict__ cls, float* __restrict__ x){
    int b = blockIdx.x, c = threadIdx.x;
    x[(size_t)b * NTOK * HID + c] = cls[c] + ((c & 1) ? 1.0f : 0.0f);
}

// ---------------- CSR build ----------------
__global__ void build_csr_kernel(const int* __restrict__ edge_index, int E){
    __shared__ int s_src[EMAX], s_dst[EMAX], cnt[NTOK];
    int t = threadIdx.x;
    for (int e = t; e < E; e += 64){
        s_src[e] = edge_index[e];
        s_dst[e] = edge_index[E + e];
    }
    __syncthreads();
    if (t < NTOK){
        int c = 1;
        for (int e = 0; e < E; e++) if (s_dst[e] == t) c++;
        cnt[t] = c;
    }
    __syncthreads();
    if (t == 0){
        int s = 0;
        for (int n = 0; n < NTOK; n++){ g_csr_ptr[n] = s; s += cnt[n]; }
        g_csr_ptr[NTOK] = s;
    }
    __syncthreads();
    if (t < NTOK){
        int pos = g_csr_ptr[t];
        for (int e = 0; e < E; e++) if (s_dst[e] == t) g_csr_src[pos++] = s_src[e];
        g_csr_src[pos++] = t;
    }
}

// ---------------- LayerNorm (warp-per-row, float out) ----------------
__global__ __launch_bounds__(256)
void ln_kernel(const float* __restrict__ x, float* __restrict__ y,
               const float* __restrict__ g, const float* __restrict__ b){
    int row  = blockIdx.x * 8 + (threadIdx.x >> 5);
    int lane = threadIdx.x & 31;
    const float* xr = x + (size_t)row * HID;
    float4 v0 = *(const float4*)(xr + lane*4);
    float4 v1 = *(const float4*)(xr + 128 + lane*4);
    float s = v0.x+v0.y+v0.z+v0.w + v1.x+v1.y+v1.z+v1.w;
    float mu = warpSum(s) * (1.0f / HID);
    float d0x=v0.x-mu, d0y=v0.y-mu, d0z=v0.z-mu, d0w=v0.w-mu;
    float d1x=v1.x-mu, d1y=v1.y-mu, d1z=v1.z-mu, d1w=v1.w-mu;
    float q = d0x*d0x+d0y*d0y+d0z*d0z+d0w*d0w + d1x*d1x+d1y*d1y+d1z*d1z+d1w*d1w;
    float var = warpSum(q) * (1.0f / HID);
    float inv = rsqrtf(var + 1e-5f);
    float4 g0 = *(const float4*)(g + lane*4);
    float4 g1 = *(const float4*)(g + 128 + lane*4);
    float4 b0 = *(const float4*)(b + lane*4);
    float4 b1 = *(const float4*)(b + 128 + lane*4);
    float* yr = y + (size_t)row * HID;
    float4 o0, o1;
    o0.x = d0x*inv*g0.x + b0.x; o0.y = d0y*inv*g0.y + b0.y;
    o0.z = d0z*inv*g0.z + b0.z; o0.w = d0w*inv*g0.w + b0.w;
    o1.x = d1x*inv*g1.x + b1.x; o1.y = d1y*inv*g1.y + b1.y;
    o1.z = d1z*inv*g1.z + b1.z; o1.w = d1w*inv*g1.w + b1.w;
    *(float4*)(yr + lane*4) = o0;
    *(float4*)(yr + 128 + lane*4) = o1;
}

// ---------------- per-head attention logit dots ----------------
__global__ __launch_bounds__(256)
void att_logits_kernel(const float* __restrict__ h,
                       const float* __restrict__ att_src,
                       const float* __restrict__ att_dst,
                       float* __restrict__ als, float* __restrict__ ald){
    int row = blockIdx.x;
    int w = threadIdx.x >> 5, lane = threadIdx.x & 31;
    float hv = h[(size_t)row * HID + w * DH + lane];
    float vs = warpSum(hv * att_src[w * DH + lane]);
    float vd = warpSum(hv * att_dst[w * DH + lane]);
    if (lane == 0){
        als[row * HEADS + w] = vs;
        ald[row * HEADS + w] = vd;
    }
}

// ---- fused: edge softmax + GAT aggregation + bias + residual + LN2 ----
// deg can be up to 50 (CLS node) -> strided loops over p.
__global__ __launch_bounds__(256)
void gat_fused_kernel(const float* __restrict__ h,
                      const float* __restrict__ als, const float* __restrict__ ald,
                      const float* __restrict__ bias, float* __restrict__ x,
                      float* __restrict__ y,
                      const float* __restrict__ g2, const float* __restrict__ b2){
    __shared__ float alpha_s[HEADS][64];
    __shared__ float sm[9];
    int b = blockIdx.x / NTOK, n = blockIdx.x % NTOK;
    int c = threadIdx.x;
    int head = c >> 5, lane = c & 31;
    int base = g_csr_ptr[n], deg = g_csr_ptr[n+1] - base;

    {
        float aldv = ald[(size_t)(b * NTOK + n) * HEADS + head];
        float m = -1e30f;
        for (int p = lane; p < deg; p += 32){
            int src = g_csr_src[base + p];
            float e = als[(size_t)(b * NTOK + src) * HEADS + head] + aldv;
            e = (e > 0.f) ? e : 0.2f * e;   // LeakyReLU(0.2)
            alpha_s[head][p] = e;
            m = fmaxf(m, e);
        }
        m = warpMax(m);
        float s = 0.f;
        for (int p = lane; p < deg; p += 32){
            float ex = expf(alpha_s[head][p] - m);
            alpha_s[head][p] = ex;
            s += ex;
        }
        s = warpSum(s);
        float inv = 1.0f / (s + 1e-16f);
        for (int p = lane; p < deg; p += 32)
            alpha_s[head][p] *= inv;
    }
    __syncthreads();

    float acc = 0.f;
    for (int p = 0; p < deg; p++){
        int src = g_csr_src[base + p];
        acc += alpha_s[head][p] * h[(size_t)(b * NTOK + src) * HID + c];
    }
    size_t idx = (size_t)(b * NTOK + n) * HID + c;
    float v = x[idx] + acc + bias[c];
    x[idx] = v;

    float mu = blockSum(v, sm) * (1.0f / HID);
    float d = v - mu;
    float var = blockSum(d * d, sm) * (1.0f / HID);
    float inv = rsqrtf(var + 1e-5f);
    y[idx] = d * inv * g2[c] + b2[c];
}

// ---------------- final row softmax ----------------
__global__ __launch_bounds__(256)
void softmax_kernel(const float* __restrict__ logits, float* __restrict__ out){
    __shared__ float sm[9];
    int row = blockIdx.x, t = threadIdx.x;
    float v[4];
    float m = -1e30f;
    #pragma unroll
    for (int k = 0; k < 4; k++){
        int c = t + k * 256;
        v[k] = (c < OUTD) ? logits[(size_t)row * OUTD + c] : -1e30f;
        m = fmaxf(m, v[k]);
    }
    m = blockMax(m, sm);
    float s = 0.f;
    #pragma unroll
    for (int k = 0; k < 4; k++){
        v[k] = expf(v[k] - m);
        int c = t + k * 256;
        if (c < OUTD) s += v[k];
    }
    s = blockSum(s, sm);
    float inv = 1.0f / s;
    #pragma unroll
    for (int k = 0; k < 4; k++){
        int c = t + k * 256;
        if (c < OUTD) out[(size_t)row * OUTD + c] = v[k] * inv;
    }
}

#define TG_SMEM (48*1024)

// ---------------- host launch ----------------
extern "C" void kernel_launch(void* const* d_in, const int* in_sizes, int n_in,
                              void* d_out, int out_size)
{
    const float* images  = (const float*)d_in[0];
    const int*   eidx    = (const int*)  d_in[1];
    const float* Wmap    = (const float*)d_in[2];
    const float* bmap    = (const float*)d_in[3];
    const float* cls_tok = (const float*)d_in[4];
    const float* Wgat    = (const float*)d_in[5];
    const float* att_src = (const float*)d_in[6];
    const float* att_dst = (const float*)d_in[7];
    const float* bgat    = (const float*)d_in[8];
    const float* ln1_g   = (const float*)d_in[9];
    const float* ln1_b   = (const float*)d_in[10];
    const float* ln2_g   = (const float*)d_in[11];
    const float* ln2_b   = (const float*)d_in[12];
    const float* W1      = (const float*)d_in[13];
    const float* b1      = (const float*)d_in[14];
    const float* W2      = (const float*)d_in[15];
    const float* b2      = (const float*)d_in[16];
    const float* Wout    = (const float*)d_in[17];
    const float* bout    = (const float*)d_in[18];

    int E = in_sizes[1] / 2;

    float *x, *y, *h, *mlp, *als, *ald, *logits;
    cudaGetSymbolAddress((void**)&x,      g_x);
    cudaGetSymbolAddress((void**)&y,      g_y);
    cudaGetSymbolAddress((void**)&h,      g_h);
    cudaGetSymbolAddress((void**)&mlp,    g_mlp);
    cudaGetSymbolAddress((void**)&als,    g_als);
    cudaGetSymbolAddress((void**)&ald,    g_ald);
    cudaGetSymbolAddress((void**)&logits, g_logits);

    cudaFuncSetAttribute(tgemm<0>, cudaFuncAttributeMaxDynamicSharedMemorySize, TG_SMEM);
    cudaFuncSetAttribute(tgemm<2>, cudaFuncAttributeMaxDynamicSharedMemorySize, TG_SMEM);
    cudaFuncSetAttribute(tgemm<3>, cudaFuncAttributeMaxDynamicSharedMemorySize, TG_SMEM);
    cudaFuncSetAttribute(tgemm<4>, cudaFuncAttributeMaxDynamicSharedMemorySize, TG_SMEM);

    // patch embed: tensor GEMM with image gather + bias + posemb + remap
    tgemm<4><<<dim3(HID/128, PROWS/128), 256, TG_SMEM>>>(images, 0, Wmap, HID, x, HID,
                                                         PROWS, HID, INPUTD, bmap);
    cls_init_kernel<<<BATCH, HID>>>(cls_tok, x);
    build_csr_kernel<<<1, 64>>>(eidx, E);

    for (int l = 0; l < 4; l++){
        ln_kernel<<<ROWS/8, 256>>>(x, y, ln1_g + l*HID, ln1_b + l*HID);
        tgemm<0><<<dim3(HID/128, ROWS/128), 256, TG_SMEM>>>(y, HID, Wgat + (size_t)l*HID*HID, HID,
                                                            h, HID, ROWS, HID, HID, nullptr);
        att_logits_kernel<<<ROWS, 256>>>(h, att_src + l*HID, att_dst + l*HID, als, ald);
        gat_fused_kernel<<<ROWS, 256>>>(h, als, ald, bgat + l*HID, x, y,
                                        ln2_g + l*HID, ln2_b + l*HID);

        tgemm<2><<<dim3(MLPD/128, ROWS/128), 256, TG_SMEM>>>(y, HID, W1 + (size_t)l*HID*MLPD, MLPD,
                                                             mlp, MLPD, ROWS, MLPD, HID, b1 + l*MLPD);
        tgemm<3><<<dim3(HID/128, ROWS/128), 256, TG_SMEM>>>(mlp, MLPD, W2 + (size_t)l*MLPD*HID, HID,
                                                            x, HID, ROWS, HID, MLPD, b2 + l*HID);
    }

    gemm64<<<dim3((OUTD+63)/64, BATCH/64), 256>>>(x, NTOK*HID, Wout, OUTD,
                                                  logits, OUTD, BATCH, OUTD, HID, bout);
    softmax_kernel<<<BATCH, 256>>>(logits, (float*)d_out);
    (void)n_in; (void)out_size;
}